// round 13
// baseline (speedup 1.0000x reference)
#include <cuda_runtime.h>
#include <cuda_fp16.h>
#include <cstdint>

#define MEANC 0.1307f
#define STDC  0.3081f
#define NIN   784
#define NH    2048
#define NOUT  10
#define NHNH  (NH * NH)
#define NSEG  16

// ---------------- device scratch ----------------
__device__ __half g_Af[4][NHNH];     // buf0: AH,AL ; buf1: AH,AL
__device__ __half g_WT[4][NHNH];     // weight^T fp16
__device__ float g_part[2][NSEG * NOUT * NH];
__device__ float g_xa[NH], g_xb[NH], g_low[NH], g_high[NH];
__device__ float g_wl[4 * NH], g_wh[4 * NH], g_bhr[4 * NH];
__device__ float g_bh[NH], g_bl[NH];
__device__ float g_x0[NIN], g_l0[NIN], g_h0[NIN];
__device__ float g_x5[NOUT];
__device__ int   g_cnt;
__device__ int   g_cnt2;
__device__ int   g_gen;

// ---------------- helpers ----------------
__device__ __forceinline__ uint32_t smem_u32(const void* p) {
    uint32_t a;
    asm("{ .reg .u64 t; cvta.to.shared.u64 t, %1; cvt.u32.u64 %0, t; }" : "=r"(a) : "l"(p));
    return a;
}

__device__ __forceinline__ void wred3(float& a, float& b, float& c) {
    const unsigned F = 0xffffffffu;
    #pragma unroll
    for (int o = 16; o > 0; o >>= 1) {
        a += __shfl_down_sync(F, a, o);
        b += __shfl_down_sync(F, b, o);
        c += __shfl_down_sync(F, c, o);
    }
}

// DeepPoly relu diag from bounds
__device__ __forceinline__ void mk_diag(float l, float h, float& wlv, float& whv, float& brv) {
    bool cr = (l < 0.f) && (h > 0.f);
    float denom = cr ? (h - l) : 1.f;
    float ubs = cr ? h / denom : 0.f;
    float ubi = cr ? -(l * h) / denom : 0.f;
    float lam = (l * l > h * h) ? 0.f : 1.f;
    float keep = (h <= 0.f) ? 0.f : 1.f;
    whv = cr ? ubs : keep;
    wlv = cr ? lam : keep;
    brv = ubi;
}

// ---------------- small kernels ----------------
__global__ void normalize_k(const float* x, const float* lo, const float* hi,
                            float* x0, float* l0, float* h0, int n) {
    int i = blockIdx.x * blockDim.x + threadIdx.x;
    if (i < n) {
        x0[i] = (x[i] - MEANC) / STDC;
        l0[i] = (lo[i] - MEANC) / STDC;
        h0[i] = (hi[i] - MEANC) / STDC;
    }
}

// layer 0: warp-per-row fused matvec + box + diag0 + relu(x); resets skchain barrier state
__global__ void box0_k(const float* __restrict__ W0, const float* __restrict__ x0,
                       const float* __restrict__ b0, const float* __restrict__ l0,
                       const float* __restrict__ h0, float* __restrict__ xa,
                       float* __restrict__ wl, float* __restrict__ wh,
                       float* __restrict__ bhr, int* __restrict__ cnt2, int* __restrict__ gen) {
    int w = threadIdx.x >> 5, lane = threadIdx.x & 31;
    int m = blockIdx.x * 8 + w;
    const float4* W4 = (const float4*)(W0 + (size_t)m * NIN);
    const float4* x4 = (const float4*)x0;
    const float4* l4 = (const float4*)l0;
    const float4* h4 = (const float4*)h0;
    float sx = 0.f, sh = 0.f, sl = 0.f;
    #pragma unroll
    for (int it = 0; it < 7; ++it) {
        int k4 = lane + it * 32;
        if (k4 < NIN / 4) {
            float4 wv = W4[k4], xv = x4[k4], lv = l4[k4], hv = h4[k4];
            #define P(c) { sx += wv.c * xv.c; \
                           sh += (wv.c >= 0.f) ? wv.c * hv.c : wv.c * lv.c; \
                           sl += (wv.c >= 0.f) ? wv.c * lv.c : wv.c * hv.c; }
            P(x) P(y) P(z) P(w)
            #undef P
        }
    }
    wred3(sx, sh, sl);
    if (lane == 0) {
        float bb = b0[m];
        float wlv, whv, brv;
        mk_diag(sl + bb, sh + bb, wlv, whv, brv);
        wl[m] = wlv; wh[m] = whv; bhr[m] = brv;
        xa[m] = fmaxf(sx + bb, 0.f);
    }
    if (blockIdx.x == 0 && threadIdx.x == 0) { *cnt2 = 0; *gen = 0; }
}

// chain start: warp-per-row fused matvec + relu-backsub transform, fp16 A emission.
__global__ void relu_bs_first_k(const float* __restrict__ W, const float* __restrict__ xin,
                                const float* __restrict__ bi,
                                const float* __restrict__ wld, const float* __restrict__ whd,
                                const float* __restrict__ bhrd, const float* __restrict__ bj,
                                __half* __restrict__ AH, __half* __restrict__ AL,
                                float* __restrict__ bh, float* __restrict__ bl,
                                float* __restrict__ xout,
                                float* __restrict__ lowv, float* __restrict__ highv,
                                int* __restrict__ cnt) {
    int w = threadIdx.x >> 5, lane = threadIdx.x & 31;
    int m = blockIdx.x * 8 + w;
    size_t base = (size_t)m * NH;
    const float4* W4 = (const float4*)(W + base);
    const float4* wl4 = (const float4*)wld;
    const float4* wh4 = (const float4*)whd;
    const float4* br4 = (const float4*)bhrd;
    const float4* bj4 = (const float4*)bj;
    const float4* x4 = (const float4*)xin;
    __half2* AH2 = (__half2*)(AH + base);
    __half2* AL2 = (__half2*)(AL + base);
    float sh = 0.f, sl = 0.f, sx = 0.f;
    #pragma unroll 4
    for (int it = 0; it < 16; ++it) {
        int k4 = lane + it * 32;
        float4 wv = W4[k4], whv = wh4[k4], wlv = wl4[k4], brv = br4[k4], bjv = bj4[k4], xv = x4[k4];
        float oh[4], ol[4];
        #define P(i, c) { float mask = (whv.c != 0.f) ? 1.f : 0.f; \
                          oh[i] = (wv.c > 0.f ? wv.c * whv.c : wv.c * wlv.c) * mask; \
                          ol[i] = (wv.c > 0.f ? wv.c * wlv.c : wv.c * whv.c) * mask; \
                          sh += fmaxf(wv.c, 0.f) * mask * brv.c + oh[i] * bjv.c; \
                          sl += fminf(wv.c, 0.f) * mask * brv.c + ol[i] * bjv.c; \
                          sx += wv.c * xv.c; }
        P(0, x) P(1, y) P(2, z) P(3, w)
        #undef P
        AH2[k4 * 2]     = __floats2half2_rn(oh[0], oh[1]);
        AH2[k4 * 2 + 1] = __floats2half2_rn(oh[2], oh[3]);
        AL2[k4 * 2]     = __floats2half2_rn(ol[0], ol[1]);
        AL2[k4 * 2 + 1] = __floats2half2_rn(ol[2], ol[3]);
    }
    wred3(sh, sl, sx);
    if (lane == 0) {
        float bb = bi[m];
        bh[m] = bb + sh;
        bl[m] = bb + sl;
        xout[m] = sx + bb;
    }
    if (threadIdx.x < 8) {
        int mm = blockIdx.x * 8 + threadIdx.x;
        lowv[mm] = 0.f;
        highv[mm] = 0.f;
    }
    if (blockIdx.x == 0 && threadIdx.x == 0) *cnt = 0;
}

// single-launch transpose of all 4 weights to fp16 (z = weight index)
__global__ void wsplit4_k(const float* __restrict__ W0, const float* __restrict__ W1,
                          const float* __restrict__ W2, const float* __restrict__ W3,
                          __half* __restrict__ WT) {
    int z = blockIdx.z;
    const float* W = (z == 0) ? W0 : (z == 1) ? W1 : (z == 2) ? W2 : W3;
    int fi = (z == 0) ? NIN : NH;
    __half* Th = WT + (size_t)z * NHNH;
    int nb = blockIdx.x * 32;
    if (z == 0 && nb >= 896) return;
    __shared__ float t[32][33];
    int tx = threadIdx.x, ty = threadIdx.y;
    int kb = blockIdx.y * 32;
    #pragma unroll
    for (int i = 0; i < 4; ++i) {
        int k = kb + ty + i * 8, n = nb + tx;
        t[ty + i * 8][tx] = (n < fi) ? W[(size_t)k * fi + n] : 0.f;
    }
    __syncthreads();
    #pragma unroll
    for (int i = 0; i < 4; ++i) {
        int n = nb + ty + i * 8, k = kb + tx;
        Th[(size_t)n * NH + k] = __float2half(t[tx][ty + i * 8]);
    }
}

// ---------------- persistent layer-4 skinny chain (one launch) ----------------
__device__ __forceinline__ void gbar(int* cnt, int* gen, int target) {
    __syncthreads();
    __threadfence();
    if (threadIdx.x == 0) {
        int v = atomicAdd(cnt, 1);
        if (v == 127) {
            atomicExch(cnt, 0);
            __threadfence();
            atomicAdd(gen, 1);
        } else {
            while (atomicAdd(gen, 0) < target) { }
        }
        __threadfence();
    }
    __syncthreads();
}

__device__ void sk_phase(const float* __restrict__ PinH, const float* __restrict__ PinL,
                         const float* __restrict__ Wfirst, const float* __restrict__ xq,
                         const float* __restrict__ wld, const float* __restrict__ whd,
                         const float* __restrict__ bhrd, const float* __restrict__ bj,
                         const float* __restrict__ Wj,
                         float* __restrict__ PoutH, float* __restrict__ PoutL,
                         float* __restrict__ bh, float* __restrict__ bl,
                         float* __restrict__ x5, int Ng,
                         float (*sH)[128], float (*sL)[128]) {
    const int t = threadIdx.x;
    const int seg = blockIdx.y;
    const int k0 = seg * 128;
    const bool dobias = (blockIdx.x == 0);
    float bHp[NOUT], bLp[NOUT], bXp[NOUT];
    #pragma unroll
    for (int m = 0; m < NOUT; ++m) { bHp[m] = 0.f; bLp[m] = 0.f; bXp[m] = 0.f; }
    {
        int k = k0 + t;
        float whk = whd[k], wlk = wld[k], brk = bhrd[k], bjk = bj[k];
        float mask = (whk != 0.f) ? 1.f : 0.f;
        float xqk = (Wfirst && dobias) ? xq[k] : 0.f;
        #pragma unroll
        for (int m = 0; m < NOUT; ++m) {
            float aH, aL;
            if (Wfirst) {
                aH = Wfirst[(size_t)m * NH + k];
                aL = aH;
            } else {
                aH = 0.f; aL = 0.f;
                #pragma unroll
                for (int s = 0; s < NSEG; ++s) {
                    aH += PinH[(size_t)(s * NOUT + m) * NH + k];
                    aL += PinL[(size_t)(s * NOUT + m) * NH + k];
                }
            }
            float oh = (aH > 0.f ? aH * whk : aH * wlk) * mask;
            float ol = (aL > 0.f ? aL * wlk : aL * whk) * mask;
            sH[m][t] = oh;
            sL[m][t] = ol;
            if (dobias) {
                bHp[m] += fmaxf(aH, 0.f) * mask * brk + oh * bjk;
                bLp[m] += fminf(aL, 0.f) * mask * brk + ol * bjk;
                if (Wfirst) bXp[m] += aH * xqk;
            }
        }
    }
    __syncthreads();
    if (dobias) {
        #pragma unroll
        for (int m = 0; m < NOUT; ++m) {
            float vH = bHp[m], vL = bLp[m], vX = bXp[m];
            wred3(vH, vL, vX);
            if ((t & 31) == 0) {
                atomicAdd(&bh[m], vH);
                atomicAdd(&bl[m], vL);
                if (Wfirst) atomicAdd(&x5[m], vX);
            }
        }
    }
    int n0 = blockIdx.x * 256 + t;
    int n1 = n0 + 128;
    float aH0[NOUT], aL0[NOUT], aH1[NOUT], aL1[NOUT];
    #pragma unroll
    for (int m = 0; m < NOUT; ++m) { aH0[m] = 0.f; aL0[m] = 0.f; aH1[m] = 0.f; aL1[m] = 0.f; }
    bool v0 = (n0 < Ng), v1 = (n1 < Ng);
    for (int kk = 0; kk < 128; ++kk) {
        const float* wr = Wj + (size_t)(k0 + kk) * Ng;
        float w0 = v0 ? wr[n0] : 0.f;
        float w1 = v1 ? wr[n1] : 0.f;
        #pragma unroll
        for (int m = 0; m < NOUT; ++m) {
            float h = sH[m][kk], l = sL[m][kk];
            aH0[m] += h * w0; aL0[m] += l * w0;
            aH1[m] += h * w1; aL1[m] += l * w1;
        }
    }
    #pragma unroll
    for (int m = 0; m < NOUT; ++m) {
        size_t rb = (size_t)(seg * NOUT + m) * NH;
        if (v0) { PoutH[rb + n0] = aH0[m]; PoutL[rb + n0] = aL0[m]; }
        if (v1) { PoutH[rb + n1] = aH1[m]; PoutL[rb + n1] = aL1[m]; }
    }
}

__global__ void __launch_bounds__(128) skchain_k(
    const float* __restrict__ W4v, const float* __restrict__ xq,
    const float* __restrict__ W3, const float* __restrict__ W2,
    const float* __restrict__ W1, const float* __restrict__ W0,
    const float* __restrict__ wl, const float* __restrict__ wh, const float* __restrict__ bhr,
    const float* __restrict__ b3, const float* __restrict__ b2,
    const float* __restrict__ b1, const float* __restrict__ b0,
    float* __restrict__ P0H, float* __restrict__ P0L,
    float* __restrict__ P1H, float* __restrict__ P1L,
    float* __restrict__ bh, float* __restrict__ bl, float* __restrict__ x5,
    const float* __restrict__ l0, const float* __restrict__ h0,
    float* __restrict__ out, int* __restrict__ cnt2, int* __restrict__ gen)
{
    __shared__ float sH[NOUT][128], sL[NOUT][128];
    sk_phase(nullptr, nullptr, W4v, xq, wl + 3 * NH, wh + 3 * NH, bhr + 3 * NH, b3,
             W3, P0H, P0L, bh, bl, x5, NH, sH, sL);
    gbar(cnt2, gen, 1);
    sk_phase(P0H, P0L, nullptr, nullptr, wl + 2 * NH, wh + 2 * NH, bhr + 2 * NH, b2,
             W2, P1H, P1L, bh, bl, x5, NH, sH, sL);
    gbar(cnt2, gen, 2);
    sk_phase(P1H, P1L, nullptr, nullptr, wl + NH, wh + NH, bhr + NH, b1,
             W1, P0H, P0L, bh, bl, x5, NH, sH, sL);
    gbar(cnt2, gen, 3);
    sk_phase(P0H, P0L, nullptr, nullptr, wl, wh, bhr, b0,
             W0, P1H, P1L, bh, bl, x5, NIN, sH, sL);
    gbar(cnt2, gen, 4);

    // final interval box: blocks 0..9 (flattened) each handle one output row
    int bid = blockIdx.y * gridDim.x + blockIdx.x;
    if (bid < NOUT) {
        int m = bid, t = threadIdx.x;
        float shh = 0.f, sll = 0.f;
        for (int n = t; n < NIN; n += 128) {
            float ah = 0.f, al = 0.f;
            #pragma unroll
            for (int s = 0; s < NSEG; ++s) {
                ah += P1H[(size_t)(s * NOUT + m) * NH + n];
                al += P1L[(size_t)(s * NOUT + m) * NH + n];
            }
            float l = l0[n], h = h0[n];
            shh += (ah >= 0.f) ? ah * h : ah * l;
            sll += (al >= 0.f) ? al * l : al * h;
        }
        const unsigned F = 0xffffffffu;
        #pragma unroll
        for (int o = 16; o > 0; o >>= 1) {
            shh += __shfl_down_sync(F, shh, o);
            sll += __shfl_down_sync(F, sll, o);
        }
        __shared__ float rh[4], rl[4];
        if ((t & 31) == 0) { rh[t >> 5] = shh; rl[t >> 5] = sll; }
        __syncthreads();
        if (t == 0) {
            shh = rh[0] + rh[1] + rh[2] + rh[3];
            sll = rl[0] + rl[1] + rl[2] + rl[3];
            out[m] = x5[m];
            out[NOUT + m] = bl[m] + sll;
            out[2 * NOUT + m] = bh[m] + shh;
        }
    }
}

// ---------------- fused H/L fp16 GEMM with transform/box epilogue ----------------
#define ROWB  272
#define MATB  (128 * ROWB)
#define STAGE (3 * MATB)
#define GSMEM (2 * STAGE)

__device__ __forceinline__ void ldsm4(uint32_t* r, uint32_t addr) {
    asm volatile("ldmatrix.sync.aligned.m8n8.x4.shared.b16 {%0,%1,%2,%3}, [%4];"
                 : "=r"(r[0]), "=r"(r[1]), "=r"(r[2]), "=r"(r[3]) : "r"(addr));
}
__device__ __forceinline__ void mma16816(float* c, const uint32_t* a, const uint32_t* b) {
    asm volatile(
        "mma.sync.aligned.m16n8k16.row.col.f32.f16.f16.f32 "
        "{%0,%1,%2,%3}, {%4,%5,%6,%7}, {%8,%9}, {%0,%1,%2,%3};"
        : "+f"(c[0]), "+f"(c[1]), "+f"(c[2]), "+f"(c[3])
        : "r"(a[0]), "r"(a[1]), "r"(a[2]), "r"(a[3]), "r"(b[0]), "r"(b[1]));
}

__device__ __forceinline__ void issue_chunk(uint32_t sb, int slot,
                                            const __half* Af, const __half* B,
                                            int row0, int col0, int k0, int tid) {
    uint32_t sbase = sb + slot * STAGE;
    #pragma unroll
    for (int i = 0; i < 24; ++i) {
        int q = tid + (i << 8);
        int mat = q >> 11;
        int r = (q >> 4) & 127;
        int g = q & 15;
        const __half* src;
        int grow;
        if (mat < 2) { src = Af + ((size_t)mat << 22); grow = row0 + r; }
        else         { src = B;                        grow = col0 + r; }
        const void* gp = src + (size_t)grow * NH + k0 + (g << 3);
        uint32_t sp = sbase + mat * MATB + r * ROWB + (g << 4);
        asm volatile("cp.async.cg.shared.global [%0], [%1], 16;" :: "r"(sp), "l"(gp));
    }
    asm volatile("cp.async.commit_group;" ::: "memory");
}

__global__ void __launch_bounds__(256, 1) hgemm_k(const __half* __restrict__ Af,
                                               const __half* __restrict__ B,
                                               __half* __restrict__ AoutH, __half* __restrict__ AoutL,
                                               const float* __restrict__ wld, const float* __restrict__ whd,
                                               const float* __restrict__ bhrd, const float* __restrict__ bjv,
                                               float* __restrict__ bh, float* __restrict__ bl,
                                               const float* __restrict__ l0, const float* __restrict__ h0,
                                               float* __restrict__ lowv, float* __restrict__ highv,
                                               int Ng, int mode,
                                               float* __restrict__ dwl, float* __restrict__ dwh,
                                               float* __restrict__ dbhr, float* __restrict__ xvec,
                                               const float* __restrict__ b4v, float* __restrict__ x5v,
                                               int* __restrict__ cnt) {
    extern __shared__ char smem[];
    const uint32_t sb = smem_u32(smem);
    const int tid = threadIdx.x, lane = tid & 31, wid = tid >> 5;
    const int row0 = blockIdx.y * 128, col0 = blockIdx.x * 128;
    const int half = wid >> 2, wq = wid & 3;
    const int warpM = (wq & 1) << 6, warpN = (wq >> 1) << 6;

    float acc[4][8][4];
    #pragma unroll
    for (int mi = 0; mi < 4; ++mi)
        #pragma unroll
        for (int ni = 0; ni < 8; ++ni)
            #pragma unroll
            for (int e = 0; e < 4; ++e) acc[mi][ni][e] = 0.f;

    issue_chunk(sb, 0, Af, B, row0, col0, 0, tid);

    const uint32_t aoff = (uint32_t)((lane & 15) * ROWB + ((lane >> 4) << 4));
    const uint32_t boff = (uint32_t)(((((lane >> 4) & 1) << 3) + (lane & 7)) * ROWB + (((lane >> 3) & 1) << 4));

    uint32_t A0[4][4], B0[4][4], A1[4][4], B1[4][4];

    const int CHUNKS = 16;
    for (int c = 0; c < CHUNKS; ++c) {
        asm volatile("cp.async.wait_group 0;" ::: "memory");
        __syncthreads();
        if (c + 1 < CHUNKS)
            issue_chunk(sb, (c + 1) & 1, Af, B, row0, col0, (c + 1) * 128, tid);

        uint32_t st = sb + (c & 1) * STAGE;
        uint32_t sA = st + half * MATB + warpM * ROWB + aoff;
        uint32_t sB = st + 2 * MATB + warpN * ROWB + boff;

        #define LDF(Ab, Bb, ko) do { \
            _Pragma("unroll") \
            for (int mi = 0; mi < 4; ++mi) ldsm4(Ab[mi], sA + mi * (16 * ROWB) + (ko)); \
            _Pragma("unroll") \
            for (int pi = 0; pi < 4; ++pi) ldsm4(Bb[pi], sB + pi * (16 * ROWB) + (ko)); \
        } while (0)
        #define MMAF(Ab, Bb) do { \
            _Pragma("unroll") \
            for (int mi = 0; mi < 4; ++mi) \
                _Pragma("unroll") \
                for (int ni = 0; ni < 8; ++ni) \
                    mma16816(acc[mi][ni], Ab[mi], &Bb[ni >> 1][(ni & 1) << 1]); \
        } while (0)

        LDF(A0, B0, 0);
        LDF(A1, B1, 32);
        MMAF(A0, B0);
        LDF(A0, B0, 64);
        MMAF(A1, B1);
        LDF(A1, B1, 96);
        MMAF(A0, B0);
        LDF(A0, B0, 128);
        MMAF(A1, B1);
        LDF(A1, B1, 160);
        MMAF(A0, B0);
        LDF(A0, B0, 192);
        MMAF(A1, B1);
        LDF(A1, B1, 224);
        MMAF(A0, B0);
        MMAF(A1, B1);
        #undef LDF
        #undef MMAF
    }

    float rowsum[4][2];
    #pragma unroll
    for (int mi = 0; mi < 4; ++mi) { rowsum[mi][0] = 0.f; rowsum[mi][1] = 0.f; }

    if (mode == 1) {
        __half* Aout = half ? AoutL : AoutH;
        #pragma unroll
        for (int ni = 0; ni < 8; ++ni) {
            int gc = col0 + warpN + ni * 8 + ((lane & 3) << 1);
            float wh0 = whd[gc], wh1 = whd[gc + 1];
            float wl0 = wld[gc], wl1 = wld[gc + 1];
            float br0 = bhrd[gc], br1 = bhrd[gc + 1];
            float bj0 = bjv[gc], bj1 = bjv[gc + 1];
            float m0 = (wh0 != 0.f) ? 1.f : 0.f, m1 = (wh1 != 0.f) ? 1.f : 0.f;
            #pragma unroll
            for (int mi = 0; mi < 4; ++mi)
                #pragma unroll
                for (int e = 0; e < 2; ++e) {
                    float v0 = acc[mi][ni][2 * e], v1 = acc[mi][ni][2 * e + 1];
                    float t0, t1, s;
                    if (half == 0) {
                        t0 = (v0 > 0.f ? v0 * wh0 : v0 * wl0) * m0;
                        t1 = (v1 > 0.f ? v1 * wh1 : v1 * wl1) * m1;
                        s = fmaxf(v0, 0.f) * m0 * br0 + t0 * bj0 + fmaxf(v1, 0.f) * m1 * br1 + t1 * bj1;
                    } else {
                        t0 = (v0 > 0.f ? v0 * wl0 : v0 * wh0) * m0;
                        t1 = (v1 > 0.f ? v1 * wl1 : v1 * wh1) * m1;
                        s = fminf(v0, 0.f) * m0 * br0 + t0 * bj0 + fminf(v1, 0.f) * m1 * br1 + t1 * bj1;
                    }
                    rowsum[mi][e] += s;
                    int gr = row0 + warpM + mi * 16 + (lane >> 2) + e * 8;
                    *reinterpret_cast<__half2*>(Aout + (size_t)gr * NH + gc) = __floats2half2_rn(t0, t1);
                }
        }
        float* bacc = half ? bl : bh;
        #pragma unroll
        for (int mi = 0; mi < 4; ++mi)
            #pragma unroll
            for (int e = 0; e < 2; ++e) {
                float s = rowsum[mi][e];
                s += __shfl_xor_sync(0xffffffffu, s, 1);
                s += __shfl_xor_sync(0xffffffffu, s, 2);
                if ((lane & 3) == 0) {
                    int gr = row0 + warpM + mi * 16 + (lane >> 2) + e * 8;
                    atomicAdd(&bacc[gr], s);
                }
            }
    } else {
        #pragma unroll
        for (int ni = 0; ni < 8; ++ni) {
            int gc = col0 + warpN + ni * 8 + ((lane & 3) << 1);
            float L0 = (gc < Ng) ? l0[gc] : 0.f;
            float H0 = (gc < Ng) ? h0[gc] : 0.f;
            float L1 = (gc + 1 < Ng) ? l0[gc + 1] : 0.f;
            float H1 = (gc + 1 < Ng) ? h0[gc + 1] : 0.f;
            #pragma unroll
            for (int mi = 0; mi < 4; ++mi)
                #pragma unroll
                for (int e = 0; e < 2; ++e) {
                    float v0 = acc[mi][ni][2 * e], v1 = acc[mi][ni][2 * e + 1];
                    float s;
                    if (half == 0)
                        s = (v0 >= 0.f ? v0 * H0 : v0 * L0) + (v1 >= 0.f ? v1 * H1 : v1 * L1);
                    else
                        s = (v0 >= 0.f ? v0 * L0 : v0 * H0) + (v1 >= 0.f ? v1 * L1 : v1 * H1);
                    rowsum[mi][e] += s;
                }
        }
        float* outv = half ? lowv : highv;
        #pragma unroll
        for (int mi = 0; mi < 4; ++mi)
            #pragma unroll
            for (int e = 0; e < 2; ++e) {
                float s = rowsum[mi][e];
                s += __shfl_xor_sync(0xffffffffu, s, 1);
                s += __shfl_xor_sync(0xffffffffu, s, 2);
                if ((lane & 3) == 0) {
                    int gr = row0 + warpM + mi * 16 + (lane >> 2) + e * 8;
                    atomicAdd(&outv[gr], s);
                }
            }

        // ---- last-CTA tail: relu diag for this layer, relu x, seed layer-4 state ----
        __threadfence();
        __shared__ int lastf;
        if (tid == 0)
            lastf = (atomicAdd(cnt, 1) == (int)(gridDim.x * gridDim.y - 1)) ? 1 : 0;
        __syncthreads();
        if (lastf) {
            __threadfence();
            for (int k = tid; k < NH; k += 256) {
                float l = lowv[k] + bl[k];
                float h = highv[k] + bh[k];
                float wlv, whv, brv;
                mk_diag(l, h, wlv, whv, brv);
                dwl[k] = wlv; dwh[k] = whv; dbhr[k] = brv;
                xvec[k] = fmaxf(xvec[k], 0.f);
            }
            if (b4v) {
                __syncthreads();
                if (tid < NOUT) {
                    bh[tid] = b4v[tid];
                    bl[tid] = b4v[tid];
                    x5v[tid] = b4v[tid];
                }
            }
        }
    }
}

// ---------------- driver ----------------
extern "C" void kernel_launch(void* const* d_in, const int* in_sizes, int n_in,
                              void* d_out, int out_size) {
    const float* x  = (const float*)d_in[0];
    const float* lo = (const float*)d_in[1];
    const float* hi = (const float*)d_in[2];
    const float* W[5];
    const float* b[5];
    for (int i = 0; i < 5; ++i) { W[i] = (const float*)d_in[3 + 2 * i]; b[i] = (const float*)d_in[4 + 2 * i]; }
    float* out = (float*)d_out;

    cudaFuncSetAttribute(hgemm_k, cudaFuncAttributeMaxDynamicSharedMemorySize, GSMEM);

    void* p;
    __half *Af, *WT;
    cudaGetSymbolAddress(&p, g_Af); Af = (__half*)p;
    cudaGetSymbolAddress(&p, g_WT); WT = (__half*)p;
    float* P0;
    cudaGetSymbolAddress(&p, g_part); P0 = (float*)p;
    size_t q = (size_t)NSEG * NOUT * NH;
    float* P0H = P0;
    float* P0L = P0 + q;
    float* P1H = (float*)Af;            // g_Af free during layer-4 chain
    float* P1L = (float*)Af + q;
    float *xa, *xb, *lowv, *highv, *wl, *wh, *bhr, *bh, *bl, *x0, *l0, *h0, *x5;
    int *cnt, *cnt2, *gen;
    cudaGetSymbolAddress(&p, g_xa);   xa = (float*)p;
    cudaGetSymbolAddress(&p, g_xb);   xb = (float*)p;
    cudaGetSymbolAddress(&p, g_low);  lowv = (float*)p;
    cudaGetSymbolAddress(&p, g_high); highv = (float*)p;
    cudaGetSymbolAddress(&p, g_wl);   wl = (float*)p;
    cudaGetSymbolAddress(&p, g_wh);   wh = (float*)p;
    cudaGetSymbolAddress(&p, g_bhr);  bhr = (float*)p;
    cudaGetSymbolAddress(&p, g_bh);   bh = (float*)p;
    cudaGetSymbolAddress(&p, g_bl);   bl = (float*)p;
    cudaGetSymbolAddress(&p, g_x0);   x0 = (float*)p;
    cudaGetSymbolAddress(&p, g_l0);   l0 = (float*)p;
    cudaGetSymbolAddress(&p, g_h0);   h0 = (float*)p;
    cudaGetSymbolAddress(&p, g_x5);   x5 = (float*)p;
    cudaGetSymbolAddress(&p, g_cnt);  cnt = (int*)p;
    cudaGetSymbolAddress(&p, g_cnt2); cnt2 = (int*)p;
    cudaGetSymbolAddress(&p, g_gen);  gen = (int*)p;

    normalize_k<<<(NIN + 255) / 256, 256>>>(x, lo, hi, x0, l0, h0, NIN);
    wsplit4_k<<<dim3(64, 64, 4), dim3(32, 8)>>>(W[0], W[1], W[2], W[3], WT);

    // layer 0 (also resets skchain barrier state)
    box0_k<<<NH / 8, 256>>>(W[0], x0, b[0], l0, h0, xa, wl, wh, bhr, cnt2, gen);

    float* xin = xa;
    float* xout = xb;
    for (int i = 1; i < 4; ++i) {
        int cur = 0;
        relu_bs_first_k<<<NH / 8, 256>>>(W[i], xin, b[i],
                                         wl + (i - 1) * NH, wh + (i - 1) * NH, bhr + (i - 1) * NH, b[i - 1],
                                         Af, Af + (size_t)NHNH, bh, bl, xout, lowv, highv, cnt);
        for (int j = i - 1; j >= 1; --j) {
            __half* Ain = Af + (size_t)cur * 2 * NHNH;
            __half* AoH = Af + (size_t)(cur ^ 1) * 2 * NHNH;
            hgemm_k<<<dim3(16, 16), 256, GSMEM>>>(Ain, WT + (size_t)j * NHNH,
                                                  AoH, AoH + (size_t)NHNH,
                                                  wl + (j - 1) * NH, wh + (j - 1) * NH,
                                                  bhr + (j - 1) * NH, b[j - 1],
                                                  bh, bl, nullptr, nullptr, nullptr, nullptr,
                                                  NH, 1,
                                                  nullptr, nullptr, nullptr, nullptr,
                                                  nullptr, nullptr, nullptr);
            cur ^= 1;
        }
        {
            __half* Ain = Af + (size_t)cur * 2 * NHNH;
            hgemm_k<<<dim3(7, 16), 256, GSMEM>>>(Ain, WT,
                                                 nullptr, nullptr,
                                                 nullptr, nullptr, nullptr, nullptr,
                                                 bh, bl, l0, h0, lowv, highv,
                                                 NIN, 2,
                                                 wl + i * NH, wh + i * NH, bhr + i * NH, xout,
                                                 (i == 3) ? b[4] : nullptr, x5, cnt);
        }
        float* t = xin; xin = xout; xout = t;
    }

    // layer 4 (M=10): one persistent kernel (bh/bl/x5 seeded by chain-3 box tail)
    skchain_k<<<dim3(8, NSEG), 128>>>(W[4], xin, W[3], W[2], W[1], W[0],
                                      wl, wh, bhr, b[3], b[2], b[1], b[0],
                                      P0H, P0L, P1H, P1L, bh, bl, x5,
                                      l0, h0, out, cnt2, gen);
    (void)in_sizes; (void)n_in; (void)out_size;
}

// round 14
// speedup vs baseline: 1.1875x; 1.1875x over previous
#include <cuda_runtime.h>
#include <cuda_fp16.h>
#include <cstdint>

#define MEANC 0.1307f
#define STDC  0.3081f
#define NIN   784
#define NH    2048
#define NOUT  10
#define NHNH  (NH * NH)
#define NSEG  16

// ---------------- device scratch ----------------
__device__ __half g_Af[4][NHNH];     // buf0: AH,AL ; buf1: AH,AL
__device__ __half g_WT[4][NHNH];     // weight^T fp16
__device__ float g_part[2][NSEG * NOUT * NH];
__device__ float g_xa[NH], g_xb[NH], g_low[NH], g_high[NH];
__device__ float g_wl[4 * NH], g_wh[4 * NH], g_bhr[4 * NH];
__device__ float g_bh[NH], g_bl[NH];
__device__ float g_x0[NIN], g_l0[NIN], g_h0[NIN];
__device__ float g_x5[NOUT];
__device__ int   g_cnt;

// ---------------- helpers ----------------
__device__ __forceinline__ uint32_t smem_u32(const void* p) {
    uint32_t a;
    asm("{ .reg .u64 t; cvta.to.shared.u64 t, %1; cvt.u32.u64 %0, t; }" : "=r"(a) : "l"(p));
    return a;
}

__device__ __forceinline__ void wred3(float& a, float& b, float& c) {
    const unsigned F = 0xffffffffu;
    #pragma unroll
    for (int o = 16; o > 0; o >>= 1) {
        a += __shfl_down_sync(F, a, o);
        b += __shfl_down_sync(F, b, o);
        c += __shfl_down_sync(F, c, o);
    }
}

// DeepPoly relu diag from bounds
__device__ __forceinline__ void mk_diag(float l, float h, float& wlv, float& whv, float& brv) {
    bool cr = (l < 0.f) && (h > 0.f);
    float denom = cr ? (h - l) : 1.f;
    float ubs = cr ? h / denom : 0.f;
    float ubi = cr ? -(l * h) / denom : 0.f;
    float lam = (l * l > h * h) ? 0.f : 1.f;
    float keep = (h <= 0.f) ? 0.f : 1.f;
    whv = cr ? ubs : keep;
    wlv = cr ? lam : keep;
    brv = ubi;
}

// ---------------- small kernels ----------------
__global__ void normalize_k(const float* x, const float* lo, const float* hi,
                            float* x0, float* l0, float* h0, int n) {
    int i = blockIdx.x * blockDim.x + threadIdx.x;
    if (i < n) {
        x0[i] = (x[i] - MEANC) / STDC;
        l0[i] = (lo[i] - MEANC) / STDC;
        h0[i] = (hi[i] - MEANC) / STDC;
    }
}

// layer 0: warp-per-row fused matvec + box + diag0 + relu(x)
__global__ void box0_k(const float* __restrict__ W0, const float* __restrict__ x0,
                       const float* __restrict__ b0, const float* __restrict__ l0,
                       const float* __restrict__ h0, float* __restrict__ xa,
                       float* __restrict__ wl, float* __restrict__ wh,
                       float* __restrict__ bhr) {
    int w = threadIdx.x >> 5, lane = threadIdx.x & 31;
    int m = blockIdx.x * 8 + w;
    const float4* W4 = (const float4*)(W0 + (size_t)m * NIN);
    const float4* x4 = (const float4*)x0;
    const float4* l4 = (const float4*)l0;
    const float4* h4 = (const float4*)h0;
    float sx = 0.f, sh = 0.f, sl = 0.f;
    #pragma unroll
    for (int it = 0; it < 7; ++it) {
        int k4 = lane + it * 32;
        if (k4 < NIN / 4) {
            float4 wv = W4[k4], xv = x4[k4], lv = l4[k4], hv = h4[k4];
            #define P(c) { sx += wv.c * xv.c; \
                           sh += (wv.c >= 0.f) ? wv.c * hv.c : wv.c * lv.c; \
                           sl += (wv.c >= 0.f) ? wv.c * lv.c : wv.c * hv.c; }
            P(x) P(y) P(z) P(w)
            #undef P
        }
    }
    wred3(sx, sh, sl);
    if (lane == 0) {
        float bb = b0[m];
        float wlv, whv, brv;
        mk_diag(sl + bb, sh + bb, wlv, whv, brv);
        wl[m] = wlv; wh[m] = whv; bhr[m] = brv;
        xa[m] = fmaxf(sx + bb, 0.f);
    }
}

// chain start: warp-per-row fused matvec + relu-backsub transform, fp16 A emission.
__global__ void relu_bs_first_k(const float* __restrict__ W, const float* __restrict__ xin,
                                const float* __restrict__ bi,
                                const float* __restrict__ wld, const float* __restrict__ whd,
                                const float* __restrict__ bhrd, const float* __restrict__ bj,
                                __half* __restrict__ AH, __half* __restrict__ AL,
                                float* __restrict__ bh, float* __restrict__ bl,
                                float* __restrict__ xout,
                                float* __restrict__ lowv, float* __restrict__ highv,
                                int* __restrict__ cnt) {
    int w = threadIdx.x >> 5, lane = threadIdx.x & 31;
    int m = blockIdx.x * 8 + w;
    size_t base = (size_t)m * NH;
    const float4* W4 = (const float4*)(W + base);
    const float4* wl4 = (const float4*)wld;
    const float4* wh4 = (const float4*)whd;
    const float4* br4 = (const float4*)bhrd;
    const float4* bj4 = (const float4*)bj;
    const float4* x4 = (const float4*)xin;
    __half2* AH2 = (__half2*)(AH + base);
    __half2* AL2 = (__half2*)(AL + base);
    float sh = 0.f, sl = 0.f, sx = 0.f;
    #pragma unroll 4
    for (int it = 0; it < 16; ++it) {
        int k4 = lane + it * 32;
        float4 wv = W4[k4], whv = wh4[k4], wlv = wl4[k4], brv = br4[k4], bjv = bj4[k4], xv = x4[k4];
        float oh[4], ol[4];
        #define P(i, c) { float mask = (whv.c != 0.f) ? 1.f : 0.f; \
                          oh[i] = (wv.c > 0.f ? wv.c * whv.c : wv.c * wlv.c) * mask; \
                          ol[i] = (wv.c > 0.f ? wv.c * wlv.c : wv.c * whv.c) * mask; \
                          sh += fmaxf(wv.c, 0.f) * mask * brv.c + oh[i] * bjv.c; \
                          sl += fminf(wv.c, 0.f) * mask * brv.c + ol[i] * bjv.c; \
                          sx += wv.c * xv.c; }
        P(0, x) P(1, y) P(2, z) P(3, w)
        #undef P
        AH2[k4 * 2]     = __floats2half2_rn(oh[0], oh[1]);
        AH2[k4 * 2 + 1] = __floats2half2_rn(oh[2], oh[3]);
        AL2[k4 * 2]     = __floats2half2_rn(ol[0], ol[1]);
        AL2[k4 * 2 + 1] = __floats2half2_rn(ol[2], ol[3]);
    }
    wred3(sh, sl, sx);
    if (lane == 0) {
        float bb = bi[m];
        bh[m] = bb + sh;
        bl[m] = bb + sl;
        xout[m] = sx + bb;
    }
    if (threadIdx.x < 8) {
        int mm = blockIdx.x * 8 + threadIdx.x;
        lowv[mm] = 0.f;
        highv[mm] = 0.f;
    }
    if (blockIdx.x == 0 && threadIdx.x == 0) *cnt = 0;
}

// single-launch transpose of all 4 weights to fp16 (z = weight index)
__global__ void wsplit4_k(const float* __restrict__ W0, const float* __restrict__ W1,
                          const float* __restrict__ W2, const float* __restrict__ W3,
                          __half* __restrict__ WT) {
    int z = blockIdx.z;
    const float* W = (z == 0) ? W0 : (z == 1) ? W1 : (z == 2) ? W2 : W3;
    int fi = (z == 0) ? NIN : NH;
    __half* Th = WT + (size_t)z * NHNH;
    int nb = blockIdx.x * 32;
    if (z == 0 && nb >= 896) return;
    __shared__ float t[32][33];
    int tx = threadIdx.x, ty = threadIdx.y;
    int kb = blockIdx.y * 32;
    #pragma unroll
    for (int i = 0; i < 4; ++i) {
        int k = kb + ty + i * 8, n = nb + tx;
        t[ty + i * 8][tx] = (n < fi) ? W[(size_t)k * fi + n] : 0.f;
    }
    __syncthreads();
    #pragma unroll
    for (int i = 0; i < 4; ++i) {
        int n = nb + ty + i * 8, k = kb + tx;
        Th[(size_t)n * NH + k] = __float2half(t[tx][ty + i * 8]);
    }
}

// ---------------- layer-4 fused skinny chain ----------------
// One backsub step: reads prev NSEG-seg partials (or W4 direct), relu transform,
// bias atomics (+ layer-4 x-dot when Wfirst), GEMM vs W[j], writes new partials.
__global__ void __launch_bounds__(128) skfuse_k(
    const float* __restrict__ PinH, const float* __restrict__ PinL,
    const float* __restrict__ Wfirst, const float* __restrict__ xq,
    const float* __restrict__ wld, const float* __restrict__ whd,
    const float* __restrict__ bhrd, const float* __restrict__ bj,
    const float* __restrict__ Wj,
    float* __restrict__ PoutH, float* __restrict__ PoutL,
    float* __restrict__ bh, float* __restrict__ bl, float* __restrict__ x5, int Ng)
{
    __shared__ float sH[NOUT][128], sL[NOUT][128];
    const int t = threadIdx.x;
    const int seg = blockIdx.y;
    const int k0 = seg * 128;
    const bool dobias = (blockIdx.x == 0);
    float bHp[NOUT], bLp[NOUT], bXp[NOUT];
    #pragma unroll
    for (int m = 0; m < NOUT; ++m) { bHp[m] = 0.f; bLp[m] = 0.f; bXp[m] = 0.f; }

    {
        int k = k0 + t;
        float whk = whd[k], wlk = wld[k], brk = bhrd[k], bjk = bj[k];
        float mask = (whk != 0.f) ? 1.f : 0.f;
        float xqk = (Wfirst && dobias) ? xq[k] : 0.f;
        #pragma unroll
        for (int m = 0; m < NOUT; ++m) {
            float aH, aL;
            if (Wfirst) {
                aH = Wfirst[(size_t)m * NH + k];
                aL = aH;
            } else {
                aH = 0.f; aL = 0.f;
                #pragma unroll
                for (int s = 0; s < NSEG; ++s) {
                    aH += PinH[(size_t)(s * NOUT + m) * NH + k];
                    aL += PinL[(size_t)(s * NOUT + m) * NH + k];
                }
            }
            float oh = (aH > 0.f ? aH * whk : aH * wlk) * mask;
            float ol = (aL > 0.f ? aL * wlk : aL * whk) * mask;
            sH[m][t] = oh;
            sL[m][t] = ol;
            if (dobias) {
                bHp[m] += fmaxf(aH, 0.f) * mask * brk + oh * bjk;
                bLp[m] += fminf(aL, 0.f) * mask * brk + ol * bjk;
                if (Wfirst) bXp[m] += aH * xqk;
            }
        }
    }
    __syncthreads();

    if (dobias) {
        #pragma unroll
        for (int m = 0; m < NOUT; ++m) {
            float vH = bHp[m], vL = bLp[m], vX = bXp[m];
            wred3(vH, vL, vX);
            if ((t & 31) == 0) {
                atomicAdd(&bh[m], vH);
                atomicAdd(&bl[m], vL);
                if (Wfirst) atomicAdd(&x5[m], vX);
            }
        }
    }

    int n = blockIdx.x * 128 + t;
    if (n < Ng) {
        float aH[NOUT], aL[NOUT];
        #pragma unroll
        for (int m = 0; m < NOUT; ++m) { aH[m] = 0.f; aL[m] = 0.f; }
        for (int kk = 0; kk < 128; ++kk) {
            float w = Wj[(size_t)(k0 + kk) * Ng + n];
            #pragma unroll
            for (int m = 0; m < NOUT; ++m) { aH[m] += sH[m][kk] * w; aL[m] += sL[m][kk] * w; }
        }
        #pragma unroll
        for (int m = 0; m < NOUT; ++m) {
            PoutH[(size_t)(seg * NOUT + m) * NH + n] = aH[m];
            PoutL[(size_t)(seg * NOUT + m) * NH + n] = aL[m];
        }
    }
}

// final interval box over the NSEG partials; writes d_out directly
__global__ void boxp_k(const float* __restrict__ PH, const float* __restrict__ PL,
                       const float* __restrict__ bh, const float* __restrict__ bl,
                       const float* __restrict__ l0, const float* __restrict__ h0,
                       const float* __restrict__ x5, float* __restrict__ out) {
    int m = blockIdx.x;
    float sh = 0.f, sl = 0.f, d = 0.f;
    for (int n = threadIdx.x; n < NIN; n += blockDim.x) {
        float ah = 0.f, al = 0.f;
        #pragma unroll
        for (int s = 0; s < NSEG; ++s) {
            ah += PH[(size_t)(s * NOUT + m) * NH + n];
            al += PL[(size_t)(s * NOUT + m) * NH + n];
        }
        float l = l0[n], h = h0[n];
        sh += (ah >= 0.f) ? ah * h : ah * l;
        sl += (al >= 0.f) ? al * l : al * h;
    }
    // block reduce (2 values)
    const unsigned F = 0xffffffffu;
    #pragma unroll
    for (int o = 16; o > 0; o >>= 1) {
        sh += __shfl_down_sync(F, sh, o);
        sl += __shfl_down_sync(F, sl, o);
    }
    __shared__ float rh[8], rl[8];
    int w = threadIdx.x >> 5, lane = threadIdx.x & 31;
    if (lane == 0) { rh[w] = sh; rl[w] = sl; }
    __syncthreads();
    if (threadIdx.x == 0) {
        sh = 0.f; sl = 0.f;
        for (int i = 0; i < (int)(blockDim.x >> 5); ++i) { sh += rh[i]; sl += rl[i]; }
        out[m] = x5[m];
        out[NOUT + m] = bl[m] + sl;
        out[2 * NOUT + m] = bh[m] + sh;
    }
    (void)d;
}

// ---------------- fused H/L fp16 GEMM with transform/box epilogue ----------------
#define ROWB  272
#define MATB  (128 * ROWB)
#define STAGE (3 * MATB)
#define GSMEM (2 * STAGE)

__device__ __forceinline__ void ldsm4(uint32_t* r, uint32_t addr) {
    asm volatile("ldmatrix.sync.aligned.m8n8.x4.shared.b16 {%0,%1,%2,%3}, [%4];"
                 : "=r"(r[0]), "=r"(r[1]), "=r"(r[2]), "=r"(r[3]) : "r"(addr));
}
__device__ __forceinline__ void mma16816(float* c, const uint32_t* a, const uint32_t* b) {
    asm volatile(
        "mma.sync.aligned.m16n8k16.row.col.f32.f16.f16.f32 "
        "{%0,%1,%2,%3}, {%4,%5,%6,%7}, {%8,%9}, {%0,%1,%2,%3};"
        : "+f"(c[0]), "+f"(c[1]), "+f"(c[2]), "+f"(c[3])
        : "r"(a[0]), "r"(a[1]), "r"(a[2]), "r"(a[3]), "r"(b[0]), "r"(b[1]));
}

__device__ __forceinline__ void issue_chunk(uint32_t sb, int slot,
                                            const __half* Af, const __half* B,
                                            int row0, int col0, int k0, int tid) {
    uint32_t sbase = sb + slot * STAGE;
    #pragma unroll
    for (int i = 0; i < 24; ++i) {
        int q = tid + (i << 8);
        int mat = q >> 11;
        int r = (q >> 4) & 127;
        int g = q & 15;
        const __half* src;
        int grow;
        if (mat < 2) { src = Af + ((size_t)mat << 22); grow = row0 + r; }
        else         { src = B;                        grow = col0 + r; }
        const void* gp = src + (size_t)grow * NH + k0 + (g << 3);
        uint32_t sp = sbase + mat * MATB + r * ROWB + (g << 4);
        asm volatile("cp.async.cg.shared.global [%0], [%1], 16;" :: "r"(sp), "l"(gp));
    }
    asm volatile("cp.async.commit_group;" ::: "memory");
}

__global__ void __launch_bounds__(256, 1) hgemm_k(const __half* __restrict__ Af,
                                               const __half* __restrict__ B,
                                               __half* __restrict__ AoutH, __half* __restrict__ AoutL,
                                               const float* __restrict__ wld, const float* __restrict__ whd,
                                               const float* __restrict__ bhrd, const float* __restrict__ bjv,
                                               float* __restrict__ bh, float* __restrict__ bl,
                                               const float* __restrict__ l0, const float* __restrict__ h0,
                                               float* __restrict__ lowv, float* __restrict__ highv,
                                               int Ng, int mode,
                                               float* __restrict__ dwl, float* __restrict__ dwh,
                                               float* __restrict__ dbhr, float* __restrict__ xvec,
                                               const float* __restrict__ b4v, float* __restrict__ x5v,
                                               int* __restrict__ cnt) {
    extern __shared__ char smem[];
    const uint32_t sb = smem_u32(smem);
    const int tid = threadIdx.x, lane = tid & 31, wid = tid >> 5;
    const int row0 = blockIdx.y * 128, col0 = blockIdx.x * 128;
    const int half = wid >> 2, wq = wid & 3;
    const int warpM = (wq & 1) << 6, warpN = (wq >> 1) << 6;

    float acc[4][8][4];
    #pragma unroll
    for (int mi = 0; mi < 4; ++mi)
        #pragma unroll
        for (int ni = 0; ni < 8; ++ni)
            #pragma unroll
            for (int e = 0; e < 4; ++e) acc[mi][ni][e] = 0.f;

    issue_chunk(sb, 0, Af, B, row0, col0, 0, tid);

    const uint32_t aoff = (uint32_t)((lane & 15) * ROWB + ((lane >> 4) << 4));
    const uint32_t boff = (uint32_t)(((((lane >> 4) & 1) << 3) + (lane & 7)) * ROWB + (((lane >> 3) & 1) << 4));

    uint32_t A0[4][4], B0[4][4], A1[4][4], B1[4][4];

    const int CHUNKS = 16;
    for (int c = 0; c < CHUNKS; ++c) {
        asm volatile("cp.async.wait_group 0;" ::: "memory");
        __syncthreads();
        if (c + 1 < CHUNKS)
            issue_chunk(sb, (c + 1) & 1, Af, B, row0, col0, (c + 1) * 128, tid);

        uint32_t st = sb + (c & 1) * STAGE;
        uint32_t sA = st + half * MATB + warpM * ROWB + aoff;
        uint32_t sB = st + 2 * MATB + warpN * ROWB + boff;

        #define LDF(Ab, Bb, ko) do { \
            _Pragma("unroll") \
            for (int mi = 0; mi < 4; ++mi) ldsm4(Ab[mi], sA + mi * (16 * ROWB) + (ko)); \
            _Pragma("unroll") \
            for (int pi = 0; pi < 4; ++pi) ldsm4(Bb[pi], sB + pi * (16 * ROWB) + (ko)); \
        } while (0)
        #define MMAF(Ab, Bb) do { \
            _Pragma("unroll") \
            for (int mi = 0; mi < 4; ++mi) \
                _Pragma("unroll") \
                for (int ni = 0; ni < 8; ++ni) \
                    mma16816(acc[mi][ni], Ab[mi], &Bb[ni >> 1][(ni & 1) << 1]); \
        } while (0)

        LDF(A0, B0, 0);
        LDF(A1, B1, 32);
        MMAF(A0, B0);
        LDF(A0, B0, 64);
        MMAF(A1, B1);
        LDF(A1, B1, 96);
        MMAF(A0, B0);
        LDF(A0, B0, 128);
        MMAF(A1, B1);
        LDF(A1, B1, 160);
        MMAF(A0, B0);
        LDF(A0, B0, 192);
        MMAF(A1, B1);
        LDF(A1, B1, 224);
        MMAF(A0, B0);
        MMAF(A1, B1);
        #undef LDF
        #undef MMAF
    }

    float rowsum[4][2];
    #pragma unroll
    for (int mi = 0; mi < 4; ++mi) { rowsum[mi][0] = 0.f; rowsum[mi][1] = 0.f; }

    if (mode == 1) {
        __half* Aout = half ? AoutL : AoutH;
        #pragma unroll
        for (int ni = 0; ni < 8; ++ni) {
            int gc = col0 + warpN + ni * 8 + ((lane & 3) << 1);
            float wh0 = whd[gc], wh1 = whd[gc + 1];
            float wl0 = wld[gc], wl1 = wld[gc + 1];
            float br0 = bhrd[gc], br1 = bhrd[gc + 1];
            float bj0 = bjv[gc], bj1 = bjv[gc + 1];
            float m0 = (wh0 != 0.f) ? 1.f : 0.f, m1 = (wh1 != 0.f) ? 1.f : 0.f;
            #pragma unroll
            for (int mi = 0; mi < 4; ++mi)
                #pragma unroll
                for (int e = 0; e < 2; ++e) {
                    float v0 = acc[mi][ni][2 * e], v1 = acc[mi][ni][2 * e + 1];
                    float t0, t1, s;
                    if (half == 0) {
                        t0 = (v0 > 0.f ? v0 * wh0 : v0 * wl0) * m0;
                        t1 = (v1 > 0.f ? v1 * wh1 : v1 * wl1) * m1;
                        s = fmaxf(v0, 0.f) * m0 * br0 + t0 * bj0 + fmaxf(v1, 0.f) * m1 * br1 + t1 * bj1;
                    } else {
                        t0 = (v0 > 0.f ? v0 * wl0 : v0 * wh0) * m0;
                        t1 = (v1 > 0.f ? v1 * wl1 : v1 * wh1) * m1;
                        s = fminf(v0, 0.f) * m0 * br0 + t0 * bj0 + fminf(v1, 0.f) * m1 * br1 + t1 * bj1;
                    }
                    rowsum[mi][e] += s;
                    int gr = row0 + warpM + mi * 16 + (lane >> 2) + e * 8;
                    *reinterpret_cast<__half2*>(Aout + (size_t)gr * NH + gc) = __floats2half2_rn(t0, t1);
                }
        }
        float* bacc = half ? bl : bh;
        #pragma unroll
        for (int mi = 0; mi < 4; ++mi)
            #pragma unroll
            for (int e = 0; e < 2; ++e) {
                float s = rowsum[mi][e];
                s += __shfl_xor_sync(0xffffffffu, s, 1);
                s += __shfl_xor_sync(0xffffffffu, s, 2);
                if ((lane & 3) == 0) {
                    int gr = row0 + warpM + mi * 16 + (lane >> 2) + e * 8;
                    atomicAdd(&bacc[gr], s);
                }
            }
    } else {
        #pragma unroll
        for (int ni = 0; ni < 8; ++ni) {
            int gc = col0 + warpN + ni * 8 + ((lane & 3) << 1);
            float L0 = (gc < Ng) ? l0[gc] : 0.f;
            float H0 = (gc < Ng) ? h0[gc] : 0.f;
            float L1 = (gc + 1 < Ng) ? l0[gc + 1] : 0.f;
            float H1 = (gc + 1 < Ng) ? h0[gc + 1] : 0.f;
            #pragma unroll
            for (int mi = 0; mi < 4; ++mi)
                #pragma unroll
                for (int e = 0; e < 2; ++e) {
                    float v0 = acc[mi][ni][2 * e], v1 = acc[mi][ni][2 * e + 1];
                    float s;
                    if (half == 0)
                        s = (v0 >= 0.f ? v0 * H0 : v0 * L0) + (v1 >= 0.f ? v1 * H1 : v1 * L1);
                    else
                        s = (v0 >= 0.f ? v0 * L0 : v0 * H0) + (v1 >= 0.f ? v1 * L1 : v1 * H1);
                    rowsum[mi][e] += s;
                }
        }
        float* outv = half ? lowv : highv;
        #pragma unroll
        for (int mi = 0; mi < 4; ++mi)
            #pragma unroll
            for (int e = 0; e < 2; ++e) {
                float s = rowsum[mi][e];
                s += __shfl_xor_sync(0xffffffffu, s, 1);
                s += __shfl_xor_sync(0xffffffffu, s, 2);
                if ((lane & 3) == 0) {
                    int gr = row0 + warpM + mi * 16 + (lane >> 2) + e * 8;
                    atomicAdd(&outv[gr], s);
                }
            }

        // ---- last-CTA tail: relu diag for this layer, relu x, seed layer-4 state ----
        __threadfence();
        __shared__ int lastf;
        if (tid == 0)
            lastf = (atomicAdd(cnt, 1) == (int)(gridDim.x * gridDim.y - 1)) ? 1 : 0;
        __syncthreads();
        if (lastf) {
            __threadfence();
            for (int k = tid; k < NH; k += 256) {
                float l = lowv[k] + bl[k];
                float h = highv[k] + bh[k];
                float wlv, whv, brv;
                mk_diag(l, h, wlv, whv, brv);
                dwl[k] = wlv; dwh[k] = whv; dbhr[k] = brv;
                xvec[k] = fmaxf(xvec[k], 0.f);
            }
            if (b4v) {
                __syncthreads();
                if (tid < NOUT) {
                    bh[tid] = b4v[tid];
                    bl[tid] = b4v[tid];
                    x5v[tid] = b4v[tid];
                }
            }
        }
    }
}

// ---------------- driver ----------------
extern "C" void kernel_launch(void* const* d_in, const int* in_sizes, int n_in,
                              void* d_out, int out_size) {
    const float* x  = (const float*)d_in[0];
    const float* lo = (const float*)d_in[1];
    const float* hi = (const float*)d_in[2];
    const float* W[5];
    const float* b[5];
    for (int i = 0; i < 5; ++i) { W[i] = (const float*)d_in[3 + 2 * i]; b[i] = (const float*)d_in[4 + 2 * i]; }
    float* out = (float*)d_out;

    cudaFuncSetAttribute(hgemm_k, cudaFuncAttributeMaxDynamicSharedMemorySize, GSMEM);

    void* p;
    __half *Af, *WT;
    cudaGetSymbolAddress(&p, g_Af); Af = (__half*)p;
    cudaGetSymbolAddress(&p, g_WT); WT = (__half*)p;
    float* P0;
    cudaGetSymbolAddress(&p, g_part); P0 = (float*)p;
    size_t q = (size_t)NSEG * NOUT * NH;
    float* P0H = P0;
    float* P0L = P0 + q;
    float* P1H = (float*)Af;            // g_Af free during layer-4 chain
    float* P1L = (float*)Af + q;
    float *xa, *xb, *lowv, *highv, *wl, *wh, *bhr, *bh, *bl, *x0, *l0, *h0, *x5;
    int* cnt;
    cudaGetSymbolAddress(&p, g_xa);   xa = (float*)p;
    cudaGetSymbolAddress(&p, g_xb);   xb = (float*)p;
    cudaGetSymbolAddress(&p, g_low);  lowv = (float*)p;
    cudaGetSymbolAddress(&p, g_high); highv = (float*)p;
    cudaGetSymbolAddress(&p, g_wl);   wl = (float*)p;
    cudaGetSymbolAddress(&p, g_wh);   wh = (float*)p;
    cudaGetSymbolAddress(&p, g_bhr);  bhr = (float*)p;
    cudaGetSymbolAddress(&p, g_bh);   bh = (float*)p;
    cudaGetSymbolAddress(&p, g_bl);   bl = (float*)p;
    cudaGetSymbolAddress(&p, g_x0);   x0 = (float*)p;
    cudaGetSymbolAddress(&p, g_l0);   l0 = (float*)p;
    cudaGetSymbolAddress(&p, g_h0);   h0 = (float*)p;
    cudaGetSymbolAddress(&p, g_x5);   x5 = (float*)p;
    cudaGetSymbolAddress(&p, g_cnt);  cnt = (int*)p;

    normalize_k<<<(NIN + 255) / 256, 256>>>(x, lo, hi, x0, l0, h0, NIN);
    wsplit4_k<<<dim3(64, 64, 4), dim3(32, 8)>>>(W[0], W[1], W[2], W[3], WT);

    // layer 0
    box0_k<<<NH / 8, 256>>>(W[0], x0, b[0], l0, h0, xa, wl, wh, bhr);

    float* xin = xa;
    float* xout = xb;
    for (int i = 1; i < 4; ++i) {
        int cur = 0;
        relu_bs_first_k<<<NH / 8, 256>>>(W[i], xin, b[i],
                                         wl + (i - 1) * NH, wh + (i - 1) * NH, bhr + (i - 1) * NH, b[i - 1],
                                         Af, Af + (size_t)NHNH, bh, bl, xout, lowv, highv, cnt);
        for (int j = i - 1; j >= 1; --j) {
            __half* Ain = Af + (size_t)cur * 2 * NHNH;
            __half* AoH = Af + (size_t)(cur ^ 1) * 2 * NHNH;
            hgemm_k<<<dim3(16, 16), 256, GSMEM>>>(Ain, WT + (size_t)j * NHNH,
                                                  AoH, AoH + (size_t)NHNH,
                                                  wl + (j - 1) * NH, wh + (j - 1) * NH,
                                                  bhr + (j - 1) * NH, b[j - 1],
                                                  bh, bl, nullptr, nullptr, nullptr, nullptr,
                                                  NH, 1,
                                                  nullptr, nullptr, nullptr, nullptr,
                                                  nullptr, nullptr, nullptr);
            cur ^= 1;
        }
        {
            __half* Ain = Af + (size_t)cur * 2 * NHNH;
            hgemm_k<<<dim3(7, 16), 256, GSMEM>>>(Ain, WT,
                                                 nullptr, nullptr,
                                                 nullptr, nullptr, nullptr, nullptr,
                                                 bh, bl, l0, h0, lowv, highv,
                                                 NIN, 2,
                                                 wl + i * NH, wh + i * NH, bhr + i * NH, xout,
                                                 (i == 3) ? b[4] : nullptr, x5, cnt);
        }
        float* t = xin; xin = xout; xout = t;
    }

    // layer 4 (M=10): fused fp32 skinny chain (bh/bl/x5 seeded by chain-3 box tail)
    {
        int cur = 0;
        float* PHs[2] = { P0H, P1H };
        float* PLs[2] = { P0L, P1L };
        skfuse_k<<<dim3(16, NSEG), 128>>>(nullptr, nullptr, W[4], xin,
                                          wl + 3 * NH, wh + 3 * NH, bhr + 3 * NH, b[3],
                                          W[3], PHs[cur], PLs[cur], bh, bl, x5, NH);
        for (int j = 2; j >= 1; --j) {
            skfuse_k<<<dim3(16, NSEG), 128>>>(PHs[cur], PLs[cur], nullptr, nullptr,
                                              wl + j * NH, wh + j * NH, bhr + j * NH, b[j],
                                              W[j], PHs[cur ^ 1], PLs[cur ^ 1], bh, bl, x5, NH);
            cur ^= 1;
        }
        skfuse_k<<<dim3(7, NSEG), 128>>>(PHs[cur], PLs[cur], nullptr, nullptr,
                                         wl, wh, bhr, b[0],
                                         W[0], PHs[cur ^ 1], PLs[cur ^ 1], bh, bl, x5, NIN);
        cur ^= 1;
        boxp_k<<<NOUT, 256>>>(PHs[cur], PLs[cur], bh, bl, l0, h0, x5, out);
    }
    (void)in_sizes; (void)n_in; (void)out_size;
}

// round 15
// speedup vs baseline: 1.1931x; 1.0047x over previous
#include <cuda_runtime.h>
#include <cuda_fp16.h>
#include <cstdint>

#define MEANC 0.1307f
#define STDC  0.3081f
#define NIN   784
#define NH    2048
#define NOUT  10
#define NHNH  (NH * NH)
#define NSEG  16

// ---------------- device scratch ----------------
__device__ __half g_Af[4][NHNH];     // buf0: AH,AL ; buf1: AH,AL
__device__ __half g_WT[4][NHNH];     // weight^T fp16
__device__ float g_part[2][NSEG * NOUT * NH];
__device__ float g_xa[NH], g_xb[NH], g_low[NH], g_high[NH];
__device__ float g_wl[4 * NH], g_wh[4 * NH], g_bhr[4 * NH];
__device__ float g_bh[NH], g_bl[NH];
__device__ float g_x0[NIN], g_l0[NIN], g_h0[NIN];
__device__ float g_x5[NOUT];
__device__ int   g_cnt;

// ---------------- helpers ----------------
__device__ __forceinline__ uint32_t smem_u32(const void* p) {
    uint32_t a;
    asm("{ .reg .u64 t; cvta.to.shared.u64 t, %1; cvt.u32.u64 %0, t; }" : "=r"(a) : "l"(p));
    return a;
}

__device__ __forceinline__ void wred3(float& a, float& b, float& c) {
    const unsigned F = 0xffffffffu;
    #pragma unroll
    for (int o = 16; o > 0; o >>= 1) {
        a += __shfl_down_sync(F, a, o);
        b += __shfl_down_sync(F, b, o);
        c += __shfl_down_sync(F, c, o);
    }
}

// DeepPoly relu diag from bounds
__device__ __forceinline__ void mk_diag(float l, float h, float& wlv, float& whv, float& brv) {
    bool cr = (l < 0.f) && (h > 0.f);
    float denom = cr ? (h - l) : 1.f;
    float ubs = cr ? h / denom : 0.f;
    float ubi = cr ? -(l * h) / denom : 0.f;
    float lam = (l * l > h * h) ? 0.f : 1.f;
    float keep = (h <= 0.f) ? 0.f : 1.f;
    whv = cr ? ubs : keep;
    wlv = cr ? lam : keep;
    brv = ubi;
}

// ---------------- small kernels ----------------
__global__ void normalize_k(const float* x, const float* lo, const float* hi,
                            float* x0, float* l0, float* h0, int n) {
    int i = blockIdx.x * blockDim.x + threadIdx.x;
    if (i < n) {
        x0[i] = (x[i] - MEANC) / STDC;
        l0[i] = (lo[i] - MEANC) / STDC;
        h0[i] = (hi[i] - MEANC) / STDC;
    }
}

// layer 0: warp-per-row fused matvec + box + diag0 + relu(x)
__global__ void box0_k(const float* __restrict__ W0, const float* __restrict__ x0,
                       const float* __restrict__ b0, const float* __restrict__ l0,
                       const float* __restrict__ h0, float* __restrict__ xa,
                       float* __restrict__ wl, float* __restrict__ wh,
                       float* __restrict__ bhr) {
    int w = threadIdx.x >> 5, lane = threadIdx.x & 31;
    int m = blockIdx.x * 8 + w;
    const float4* W4 = (const float4*)(W0 + (size_t)m * NIN);
    const float4* x4 = (const float4*)x0;
    const float4* l4 = (const float4*)l0;
    const float4* h4 = (const float4*)h0;
    float sx = 0.f, sh = 0.f, sl = 0.f;
    #pragma unroll
    for (int it = 0; it < 7; ++it) {
        int k4 = lane + it * 32;
        if (k4 < NIN / 4) {
            float4 wv = W4[k4], xv = x4[k4], lv = l4[k4], hv = h4[k4];
            #define P(c) { sx += wv.c * xv.c; \
                           sh += (wv.c >= 0.f) ? wv.c * hv.c : wv.c * lv.c; \
                           sl += (wv.c >= 0.f) ? wv.c * lv.c : wv.c * hv.c; }
            P(x) P(y) P(z) P(w)
            #undef P
        }
    }
    wred3(sx, sh, sl);
    if (lane == 0) {
        float bb = b0[m];
        float wlv, whv, brv;
        mk_diag(sl + bb, sh + bb, wlv, whv, brv);
        wl[m] = wlv; wh[m] = whv; bhr[m] = brv;
        xa[m] = fmaxf(sx + bb, 0.f);
    }
}

// chain start: warp-per-row fused matvec + relu-backsub transform, fp16 A emission.
__global__ void relu_bs_first_k(const float* __restrict__ W, const float* __restrict__ xin,
                                const float* __restrict__ bi,
                                const float* __restrict__ wld, const float* __restrict__ whd,
                                const float* __restrict__ bhrd, const float* __restrict__ bj,
                                __half* __restrict__ AH, __half* __restrict__ AL,
                                float* __restrict__ bh, float* __restrict__ bl,
                                float* __restrict__ xout,
                                float* __restrict__ lowv, float* __restrict__ highv,
                                int* __restrict__ cnt) {
    int w = threadIdx.x >> 5, lane = threadIdx.x & 31;
    int m = blockIdx.x * 8 + w;
    size_t base = (size_t)m * NH;
    const float4* W4 = (const float4*)(W + base);
    const float4* wl4 = (const float4*)wld;
    const float4* wh4 = (const float4*)whd;
    const float4* br4 = (const float4*)bhrd;
    const float4* bj4 = (const float4*)bj;
    const float4* x4 = (const float4*)xin;
    __half2* AH2 = (__half2*)(AH + base);
    __half2* AL2 = (__half2*)(AL + base);
    float sh = 0.f, sl = 0.f, sx = 0.f;
    #pragma unroll 4
    for (int it = 0; it < 16; ++it) {
        int k4 = lane + it * 32;
        float4 wv = W4[k4], whv = wh4[k4], wlv = wl4[k4], brv = br4[k4], bjv = bj4[k4], xv = x4[k4];
        float oh[4], ol[4];
        #define P(i, c) { float mask = (whv.c != 0.f) ? 1.f : 0.f; \
                          oh[i] = (wv.c > 0.f ? wv.c * whv.c : wv.c * wlv.c) * mask; \
                          ol[i] = (wv.c > 0.f ? wv.c * wlv.c : wv.c * whv.c) * mask; \
                          sh += fmaxf(wv.c, 0.f) * mask * brv.c + oh[i] * bjv.c; \
                          sl += fminf(wv.c, 0.f) * mask * brv.c + ol[i] * bjv.c; \
                          sx += wv.c * xv.c; }
        P(0, x) P(1, y) P(2, z) P(3, w)
        #undef P
        AH2[k4 * 2]     = __floats2half2_rn(oh[0], oh[1]);
        AH2[k4 * 2 + 1] = __floats2half2_rn(oh[2], oh[3]);
        AL2[k4 * 2]     = __floats2half2_rn(ol[0], ol[1]);
        AL2[k4 * 2 + 1] = __floats2half2_rn(ol[2], ol[3]);
    }
    wred3(sh, sl, sx);
    if (lane == 0) {
        float bb = bi[m];
        bh[m] = bb + sh;
        bl[m] = bb + sl;
        xout[m] = sx + bb;
    }
    if (threadIdx.x < 8) {
        int mm = blockIdx.x * 8 + threadIdx.x;
        lowv[mm] = 0.f;
        highv[mm] = 0.f;
    }
    if (blockIdx.x == 0 && threadIdx.x == 0) *cnt = 0;
}

// single-launch transpose of all 4 weights to fp16 (z = weight index)
__global__ void wsplit4_k(const float* __restrict__ W0, const float* __restrict__ W1,
                          const float* __restrict__ W2, const float* __restrict__ W3,
                          __half* __restrict__ WT) {
    int z = blockIdx.z;
    const float* W = (z == 0) ? W0 : (z == 1) ? W1 : (z == 2) ? W2 : W3;
    int fi = (z == 0) ? NIN : NH;
    __half* Th = WT + (size_t)z * NHNH;
    int nb = blockIdx.x * 32;
    if (z == 0 && nb >= 896) return;
    __shared__ float t[32][33];
    int tx = threadIdx.x, ty = threadIdx.y;
    int kb = blockIdx.y * 32;
    #pragma unroll
    for (int i = 0; i < 4; ++i) {
        int k = kb + ty + i * 8, n = nb + tx;
        t[ty + i * 8][tx] = (n < fi) ? W[(size_t)k * fi + n] : 0.f;
    }
    __syncthreads();
    #pragma unroll
    for (int i = 0; i < 4; ++i) {
        int n = nb + ty + i * 8, k = kb + tx;
        Th[(size_t)n * NH + k] = __float2half(t[tx][ty + i * 8]);
    }
}

// ---------------- layer-4 fused skinny chain ----------------
// One backsub step: reads prev NSEG-seg partials (or W4 direct), relu transform,
// bias atomics (+ layer-4 x-dot when Wfirst), GEMM vs W[j], writes new partials.
__global__ void __launch_bounds__(128) skfuse_k(
    const float* __restrict__ PinH, const float* __restrict__ PinL,
    const float* __restrict__ Wfirst, const float* __restrict__ xq,
    const float* __restrict__ wld, const float* __restrict__ whd,
    const float* __restrict__ bhrd, const float* __restrict__ bj,
    const float* __restrict__ Wj,
    float* __restrict__ PoutH, float* __restrict__ PoutL,
    float* __restrict__ bh, float* __restrict__ bl, float* __restrict__ x5, int Ng)
{
    __shared__ float sH[NOUT][128], sL[NOUT][128];
    const int t = threadIdx.x;
    const int seg = blockIdx.y;
    const int k0 = seg * 128;
    const bool dobias = (blockIdx.x == 0);
    float bHp[NOUT], bLp[NOUT], bXp[NOUT];
    #pragma unroll
    for (int m = 0; m < NOUT; ++m) { bHp[m] = 0.f; bLp[m] = 0.f; bXp[m] = 0.f; }

    {
        int k = k0 + t;
        float whk = whd[k], wlk = wld[k], brk = bhrd[k], bjk = bj[k];
        float mask = (whk != 0.f) ? 1.f : 0.f;
        float xqk = (Wfirst && dobias) ? xq[k] : 0.f;
        #pragma unroll
        for (int m = 0; m < NOUT; ++m) {
            float aH, aL;
            if (Wfirst) {
                aH = Wfirst[(size_t)m * NH + k];
                aL = aH;
            } else {
                aH = 0.f; aL = 0.f;
                #pragma unroll
                for (int s = 0; s < NSEG; ++s) {
                    aH += PinH[(size_t)(s * NOUT + m) * NH + k];
                    aL += PinL[(size_t)(s * NOUT + m) * NH + k];
                }
            }
            float oh = (aH > 0.f ? aH * whk : aH * wlk) * mask;
            float ol = (aL > 0.f ? aL * wlk : aL * whk) * mask;
            sH[m][t] = oh;
            sL[m][t] = ol;
            if (dobias) {
                bHp[m] += fmaxf(aH, 0.f) * mask * brk + oh * bjk;
                bLp[m] += fminf(aL, 0.f) * mask * brk + ol * bjk;
                if (Wfirst) bXp[m] += aH * xqk;
            }
        }
    }
    __syncthreads();

    if (dobias) {
        #pragma unroll
        for (int m = 0; m < NOUT; ++m) {
            float vH = bHp[m], vL = bLp[m], vX = bXp[m];
            wred3(vH, vL, vX);
            if ((t & 31) == 0) {
                atomicAdd(&bh[m], vH);
                atomicAdd(&bl[m], vL);
                if (Wfirst) atomicAdd(&x5[m], vX);
            }
        }
    }

    int n = blockIdx.x * 128 + t;
    if (n < Ng) {
        float aH[NOUT], aL[NOUT];
        #pragma unroll
        for (int m = 0; m < NOUT; ++m) { aH[m] = 0.f; aL[m] = 0.f; }
        for (int kk = 0; kk < 128; ++kk) {
            float w = Wj[(size_t)(k0 + kk) * Ng + n];
            #pragma unroll
            for (int m = 0; m < NOUT; ++m) { aH[m] += sH[m][kk] * w; aL[m] += sL[m][kk] * w; }
        }
        #pragma unroll
        for (int m = 0; m < NOUT; ++m) {
            PoutH[(size_t)(seg * NOUT + m) * NH + n] = aH[m];
            PoutL[(size_t)(seg * NOUT + m) * NH + n] = aL[m];
        }
    }
}

// final interval box over the NSEG partials; writes d_out directly
__global__ void boxp_k(const float* __restrict__ PH, const float* __restrict__ PL,
                       const float* __restrict__ bh, const float* __restrict__ bl,
                       const float* __restrict__ l0, const float* __restrict__ h0,
                       const float* __restrict__ x5, float* __restrict__ out) {
    int m = blockIdx.x;
    float sh = 0.f, sl = 0.f, d = 0.f;
    for (int n = threadIdx.x; n < NIN; n += blockDim.x) {
        float ah = 0.f, al = 0.f;
        #pragma unroll
        for (int s = 0; s < NSEG; ++s) {
            ah += PH[(size_t)(s * NOUT + m) * NH + n];
            al += PL[(size_t)(s * NOUT + m) * NH + n];
        }
        float l = l0[n], h = h0[n];
        sh += (ah >= 0.f) ? ah * h : ah * l;
        sl += (al >= 0.f) ? al * l : al * h;
    }
    // block reduce (2 values)
    const unsigned F = 0xffffffffu;
    #pragma unroll
    for (int o = 16; o > 0; o >>= 1) {
        sh += __shfl_down_sync(F, sh, o);
        sl += __shfl_down_sync(F, sl, o);
    }
    __shared__ float rh[8], rl[8];
    int w = threadIdx.x >> 5, lane = threadIdx.x & 31;
    if (lane == 0) { rh[w] = sh; rl[w] = sl; }
    __syncthreads();
    if (threadIdx.x == 0) {
        sh = 0.f; sl = 0.f;
        for (int i = 0; i < (int)(blockDim.x >> 5); ++i) { sh += rh[i]; sl += rl[i]; }
        out[m] = x5[m];
        out[NOUT + m] = bl[m] + sl;
        out[2 * NOUT + m] = bh[m] + sh;
    }
    (void)d;
}

// ---------------- fused H/L fp16 GEMM with transform/box epilogue ----------------
#define ROWB  272
#define MATB  (128 * ROWB)
#define STAGE (3 * MATB)
#define GSMEM (2 * STAGE)

__device__ __forceinline__ void ldsm4(uint32_t* r, uint32_t addr) {
    asm volatile("ldmatrix.sync.aligned.m8n8.x4.shared.b16 {%0,%1,%2,%3}, [%4];"
                 : "=r"(r[0]), "=r"(r[1]), "=r"(r[2]), "=r"(r[3]) : "r"(addr));
}
__device__ __forceinline__ void mma16816(float* c, const uint32_t* a, const uint32_t* b) {
    asm volatile(
        "mma.sync.aligned.m16n8k16.row.col.f32.f16.f16.f32 "
        "{%0,%1,%2,%3}, {%4,%5,%6,%7}, {%8,%9}, {%0,%1,%2,%3};"
        : "+f"(c[0]), "+f"(c[1]), "+f"(c[2]), "+f"(c[3])
        : "r"(a[0]), "r"(a[1]), "r"(a[2]), "r"(a[3]), "r"(b[0]), "r"(b[1]));
}

__device__ __forceinline__ void issue_chunk(uint32_t sb, int slot,
                                            const __half* Af, const __half* B,
                                            int row0, int col0, int k0, int tid) {
    uint32_t sbase = sb + slot * STAGE;
    #pragma unroll
    for (int i = 0; i < 24; ++i) {
        int q = tid + (i << 8);
        int mat = q >> 11;
        int r = (q >> 4) & 127;
        int g = q & 15;
        const __half* src;
        int grow;
        if (mat < 2) { src = Af + ((size_t)mat << 22); grow = row0 + r; }
        else         { src = B;                        grow = col0 + r; }
        const void* gp = src + (size_t)grow * NH + k0 + (g << 3);
        uint32_t sp = sbase + mat * MATB + r * ROWB + (g << 4);
        asm volatile("cp.async.cg.shared.global [%0], [%1], 16;" :: "r"(sp), "l"(gp));
    }
    asm volatile("cp.async.commit_group;" ::: "memory");
}

__global__ void __launch_bounds__(256, 1) hgemm_k(const __half* __restrict__ Af,
                                               const __half* __restrict__ B,
                                               __half* __restrict__ AoutH, __half* __restrict__ AoutL,
                                               const float* __restrict__ wld, const float* __restrict__ whd,
                                               const float* __restrict__ bhrd, const float* __restrict__ bjv,
                                               float* __restrict__ bh, float* __restrict__ bl,
                                               const float* __restrict__ l0, const float* __restrict__ h0,
                                               float* __restrict__ lowv, float* __restrict__ highv,
                                               int Ng, int mode,
                                               float* __restrict__ dwl, float* __restrict__ dwh,
                                               float* __restrict__ dbhr, float* __restrict__ xvec,
                                               const float* __restrict__ b4v, float* __restrict__ x5v,
                                               int* __restrict__ cnt) {
    extern __shared__ char smem[];
    const uint32_t sb = smem_u32(smem);
    const int tid = threadIdx.x, lane = tid & 31, wid = tid >> 5;
    const int row0 = blockIdx.y * 128, col0 = blockIdx.x * 128;
    const int half = wid >> 2, wq = wid & 3;
    const int warpM = (wq & 1) << 6, warpN = (wq >> 1) << 6;

    float acc[4][8][4];
    #pragma unroll
    for (int mi = 0; mi < 4; ++mi)
        #pragma unroll
        for (int ni = 0; ni < 8; ++ni)
            #pragma unroll
            for (int e = 0; e < 4; ++e) acc[mi][ni][e] = 0.f;

    issue_chunk(sb, 0, Af, B, row0, col0, 0, tid);

    const uint32_t aoff = (uint32_t)((lane & 15) * ROWB + ((lane >> 4) << 4));
    const uint32_t boff = (uint32_t)(((((lane >> 4) & 1) << 3) + (lane & 7)) * ROWB + (((lane >> 3) & 1) << 4));

    uint32_t A0[4][4], B0[4][4], A1[4][4], B1[4][4];

    const int CHUNKS = 16;
    for (int c = 0; c < CHUNKS; ++c) {
        asm volatile("cp.async.wait_group 0;" ::: "memory");
        __syncthreads();
        if (c + 1 < CHUNKS)
            issue_chunk(sb, (c + 1) & 1, Af, B, row0, col0, (c + 1) * 128, tid);

        uint32_t st = sb + (c & 1) * STAGE;
        uint32_t sA = st + half * MATB + warpM * ROWB + aoff;
        uint32_t sB = st + 2 * MATB + warpN * ROWB + boff;

        #define LDF(Ab, Bb, ko) do { \
            _Pragma("unroll") \
            for (int mi = 0; mi < 4; ++mi) ldsm4(Ab[mi], sA + mi * (16 * ROWB) + (ko)); \
            _Pragma("unroll") \
            for (int pi = 0; pi < 4; ++pi) ldsm4(Bb[pi], sB + pi * (16 * ROWB) + (ko)); \
        } while (0)
        #define MMAF(Ab, Bb) do { \
            _Pragma("unroll") \
            for (int mi = 0; mi < 4; ++mi) \
                _Pragma("unroll") \
                for (int ni = 0; ni < 8; ++ni) \
                    mma16816(acc[mi][ni], Ab[mi], &Bb[ni >> 1][(ni & 1) << 1]); \
        } while (0)

        LDF(A0, B0, 0);
        LDF(A1, B1, 32);
        MMAF(A0, B0);
        LDF(A0, B0, 64);
        MMAF(A1, B1);
        LDF(A1, B1, 96);
        MMAF(A0, B0);
        LDF(A0, B0, 128);
        MMAF(A1, B1);
        LDF(A1, B1, 160);
        MMAF(A0, B0);
        LDF(A0, B0, 192);
        MMAF(A1, B1);
        LDF(A1, B1, 224);
        MMAF(A0, B0);
        MMAF(A1, B1);
        #undef LDF
        #undef MMAF
    }

    float rowsum[4][2];
    #pragma unroll
    for (int mi = 0; mi < 4; ++mi) { rowsum[mi][0] = 0.f; rowsum[mi][1] = 0.f; }

    if (mode == 1) {
        __half* Aout = half ? AoutL : AoutH;
        #pragma unroll
        for (int ni = 0; ni < 8; ++ni) {
            int gc = col0 + warpN + ni * 8 + ((lane & 3) << 1);
            float wh0 = whd[gc], wh1 = whd[gc + 1];
            float wl0 = wld[gc], wl1 = wld[gc + 1];
            float br0 = bhrd[gc], br1 = bhrd[gc + 1];
            float bj0 = bjv[gc], bj1 = bjv[gc + 1];
            float m0 = (wh0 != 0.f) ? 1.f : 0.f, m1 = (wh1 != 0.f) ? 1.f : 0.f;
            #pragma unroll
            for (int mi = 0; mi < 4; ++mi)
                #pragma unroll
                for (int e = 0; e < 2; ++e) {
                    float v0 = acc[mi][ni][2 * e], v1 = acc[mi][ni][2 * e + 1];
                    float t0, t1, s;
                    if (half == 0) {
                        t0 = (v0 > 0.f ? v0 * wh0 : v0 * wl0) * m0;
                        t1 = (v1 > 0.f ? v1 * wh1 : v1 * wl1) * m1;
                        s = fmaxf(v0, 0.f) * m0 * br0 + t0 * bj0 + fmaxf(v1, 0.f) * m1 * br1 + t1 * bj1;
                    } else {
                        t0 = (v0 > 0.f ? v0 * wl0 : v0 * wh0) * m0;
                        t1 = (v1 > 0.f ? v1 * wl1 : v1 * wh1) * m1;
                        s = fminf(v0, 0.f) * m0 * br0 + t0 * bj0 + fminf(v1, 0.f) * m1 * br1 + t1 * bj1;
                    }
                    rowsum[mi][e] += s;
                    int gr = row0 + warpM + mi * 16 + (lane >> 2) + e * 8;
                    *reinterpret_cast<__half2*>(Aout + (size_t)gr * NH + gc) = __floats2half2_rn(t0, t1);
                }
        }
        float* bacc = half ? bl : bh;
        #pragma unroll
        for (int mi = 0; mi < 4; ++mi)
            #pragma unroll
            for (int e = 0; e < 2; ++e) {
                float s = rowsum[mi][e];
                s += __shfl_xor_sync(0xffffffffu, s, 1);
                s += __shfl_xor_sync(0xffffffffu, s, 2);
                if ((lane & 3) == 0) {
                    int gr = row0 + warpM + mi * 16 + (lane >> 2) + e * 8;
                    atomicAdd(&bacc[gr], s);
                }
            }
    } else {
        #pragma unroll
        for (int ni = 0; ni < 8; ++ni) {
            int gc = col0 + warpN + ni * 8 + ((lane & 3) << 1);
            float L0 = (gc < Ng) ? l0[gc] : 0.f;
            float H0 = (gc < Ng) ? h0[gc] : 0.f;
            float L1 = (gc + 1 < Ng) ? l0[gc + 1] : 0.f;
            float H1 = (gc + 1 < Ng) ? h0[gc + 1] : 0.f;
            #pragma unroll
            for (int mi = 0; mi < 4; ++mi)
                #pragma unroll
                for (int e = 0; e < 2; ++e) {
                    float v0 = acc[mi][ni][2 * e], v1 = acc[mi][ni][2 * e + 1];
                    float s;
                    if (half == 0)
                        s = (v0 >= 0.f ? v0 * H0 : v0 * L0) + (v1 >= 0.f ? v1 * H1 : v1 * L1);
                    else
                        s = (v0 >= 0.f ? v0 * L0 : v0 * H0) + (v1 >= 0.f ? v1 * L1 : v1 * H1);
                    rowsum[mi][e] += s;
                }
        }
        float* outv = half ? lowv : highv;
        #pragma unroll
        for (int mi = 0; mi < 4; ++mi)
            #pragma unroll
            for (int e = 0; e < 2; ++e) {
                float s = rowsum[mi][e];
                s += __shfl_xor_sync(0xffffffffu, s, 1);
                s += __shfl_xor_sync(0xffffffffu, s, 2);
                if ((lane & 3) == 0) {
                    int gr = row0 + warpM + mi * 16 + (lane >> 2) + e * 8;
                    atomicAdd(&outv[gr], s);
                }
            }

        // ---- last-CTA tail: relu diag for this layer, relu x, seed layer-4 state ----
        __threadfence();
        __shared__ int lastf;
        if (tid == 0)
            lastf = (atomicAdd(cnt, 1) == (int)(gridDim.x * gridDim.y - 1)) ? 1 : 0;
        __syncthreads();
        if (lastf) {
            __threadfence();
            for (int k = tid; k < NH; k += 256) {
                float l = lowv[k] + bl[k];
                float h = highv[k] + bh[k];
                float wlv, whv, brv;
                mk_diag(l, h, wlv, whv, brv);
                dwl[k] = wlv; dwh[k] = whv; dbhr[k] = brv;
                xvec[k] = fmaxf(xvec[k], 0.f);
            }
            if (b4v) {
                __syncthreads();
                if (tid < NOUT) {
                    bh[tid] = b4v[tid];
                    bl[tid] = b4v[tid];
                    x5v[tid] = b4v[tid];
                }
            }
        }
    }
}

// ---------------- driver ----------------
extern "C" void kernel_launch(void* const* d_in, const int* in_sizes, int n_in,
                              void* d_out, int out_size) {
    const float* x  = (const float*)d_in[0];
    const float* lo = (const float*)d_in[1];
    const float* hi = (const float*)d_in[2];
    const float* W[5];
    const float* b[5];
    for (int i = 0; i < 5; ++i) { W[i] = (const float*)d_in[3 + 2 * i]; b[i] = (const float*)d_in[4 + 2 * i]; }
    float* out = (float*)d_out;

    cudaFuncSetAttribute(hgemm_k, cudaFuncAttributeMaxDynamicSharedMemorySize, GSMEM);

    void* p;
    __half *Af, *WT;
    cudaGetSymbolAddress(&p, g_Af); Af = (__half*)p;
    cudaGetSymbolAddress(&p, g_WT); WT = (__half*)p;
    float* P0;
    cudaGetSymbolAddress(&p, g_part); P0 = (float*)p;
    size_t q = (size_t)NSEG * NOUT * NH;
    float* P0H = P0;
    float* P0L = P0 + q;
    float* P1H = (float*)Af;            // g_Af free during layer-4 chain
    float* P1L = (float*)Af + q;
    float *xa, *xb, *lowv, *highv, *wl, *wh, *bhr, *bh, *bl, *x0, *l0, *h0, *x5;
    int* cnt;
    cudaGetSymbolAddress(&p, g_xa);   xa = (float*)p;
    cudaGetSymbolAddress(&p, g_xb);   xb = (float*)p;
    cudaGetSymbolAddress(&p, g_low);  lowv = (float*)p;
    cudaGetSymbolAddress(&p, g_high); highv = (float*)p;
    cudaGetSymbolAddress(&p, g_wl);   wl = (float*)p;
    cudaGetSymbolAddress(&p, g_wh);   wh = (float*)p;
    cudaGetSymbolAddress(&p, g_bhr);  bhr = (float*)p;
    cudaGetSymbolAddress(&p, g_bh);   bh = (float*)p;
    cudaGetSymbolAddress(&p, g_bl);   bl = (float*)p;
    cudaGetSymbolAddress(&p, g_x0);   x0 = (float*)p;
    cudaGetSymbolAddress(&p, g_l0);   l0 = (float*)p;
    cudaGetSymbolAddress(&p, g_h0);   h0 = (float*)p;
    cudaGetSymbolAddress(&p, g_x5);   x5 = (float*)p;
    cudaGetSymbolAddress(&p, g_cnt);  cnt = (int*)p;

    normalize_k<<<(NIN + 255) / 256, 256>>>(x, lo, hi, x0, l0, h0, NIN);
    wsplit4_k<<<dim3(64, 64, 4), dim3(32, 8)>>>(W[0], W[1], W[2], W[3], WT);

    // layer 0
    box0_k<<<NH / 8, 256>>>(W[0], x0, b[0], l0, h0, xa, wl, wh, bhr);

    float* xin = xa;
    float* xout = xb;
    for (int i = 1; i < 4; ++i) {
        int cur = 0;
        relu_bs_first_k<<<NH / 8, 256>>>(W[i], xin, b[i],
                                         wl + (i - 1) * NH, wh + (i - 1) * NH, bhr + (i - 1) * NH, b[i - 1],
                                         Af, Af + (size_t)NHNH, bh, bl, xout, lowv, highv, cnt);
        for (int j = i - 1; j >= 1; --j) {
            __half* Ain = Af + (size_t)cur * 2 * NHNH;
            __half* AoH = Af + (size_t)(cur ^ 1) * 2 * NHNH;
            hgemm_k<<<dim3(16, 16), 256, GSMEM>>>(Ain, WT + (size_t)j * NHNH,
                                                  AoH, AoH + (size_t)NHNH,
                                                  wl + (j - 1) * NH, wh + (j - 1) * NH,
                                                  bhr + (j - 1) * NH, b[j - 1],
                                                  bh, bl, nullptr, nullptr, nullptr, nullptr,
                                                  NH, 1,
                                                  nullptr, nullptr, nullptr, nullptr,
                                                  nullptr, nullptr, nullptr);
            cur ^= 1;
        }
        {
            __half* Ain = Af + (size_t)cur * 2 * NHNH;
            hgemm_k<<<dim3(7, 16), 256, GSMEM>>>(Ain, WT,
                                                 nullptr, nullptr,
                                                 nullptr, nullptr, nullptr, nullptr,
                                                 bh, bl, l0, h0, lowv, highv,
                                                 NIN, 2,
                                                 wl + i * NH, wh + i * NH, bhr + i * NH, xout,
                                                 (i == 3) ? b[4] : nullptr, x5, cnt);
        }
        float* t = xin; xin = xout; xout = t;
    }

    // layer 4 (M=10): fused fp32 skinny chain (bh/bl/x5 seeded by chain-3 box tail)
    {
        int cur = 0;
        float* PHs[2] = { P0H, P1H };
        float* PLs[2] = { P0L, P1L };
        skfuse_k<<<dim3(16, NSEG), 128>>>(nullptr, nullptr, W[4], xin,
                                          wl + 3 * NH, wh + 3 * NH, bhr + 3 * NH, b[3],
                                          W[3], PHs[cur], PLs[cur], bh, bl, x5, NH);
        for (int j = 2; j >= 1; --j) {
            skfuse_k<<<dim3(16, NSEG), 128>>>(PHs[cur], PLs[cur], nullptr, nullptr,
                                              wl + j * NH, wh + j * NH, bhr + j * NH, b[j],
                                              W[j], PHs[cur ^ 1], PLs[cur ^ 1], bh, bl, x5, NH);
            cur ^= 1;
        }
        skfuse_k<<<dim3(7, NSEG), 128>>>(PHs[cur], PLs[cur], nullptr, nullptr,
                                         wl, wh, bhr, b[0],
                                         W[0], PHs[cur ^ 1], PLs[cur ^ 1], bh, bl, x5, NIN);
        cur ^= 1;
        boxp_k<<<NOUT, 256>>>(PHs[cur], PLs[cur], bh, bl, l0, h0, x5, out);
    }
    (void)in_sizes; (void)n_in; (void)out_size;
}

// round 16
// speedup vs baseline: 1.1960x; 1.0024x over previous
#include <cuda_runtime.h>
#include <cuda_fp16.h>
#include <cstdint>

#define MEANC 0.1307f
#define STDC  0.3081f
#define NIN   784
#define NH    2048
#define NOUT  10
#define NHNH  (NH * NH)
#define NSEG  16

// ---------------- device scratch ----------------
__device__ __half g_Af[4][NHNH];     // buf0: AH,AL ; buf1: AH,AL
__device__ __half g_WT[4][NHNH];     // weight^T fp16
__device__ float g_part[2][NSEG * NOUT * NH];
__device__ float g_xa[NH], g_xb[NH], g_low[NH], g_high[NH];
__device__ float g_wl[4 * NH], g_wh[4 * NH], g_bhr[4 * NH];
__device__ float g_bh[NH], g_bl[NH];
__device__ float g_x0[NIN], g_l0[NIN], g_h0[NIN];
__device__ float g_x5[NOUT];
__device__ int   g_cnt;

// ---------------- helpers ----------------
__device__ __forceinline__ uint32_t smem_u32(const void* p) {
    uint32_t a;
    asm("{ .reg .u64 t; cvta.to.shared.u64 t, %1; cvt.u32.u64 %0, t; }" : "=r"(a) : "l"(p));
    return a;
}

__device__ __forceinline__ void wred3(float& a, float& b, float& c) {
    const unsigned F = 0xffffffffu;
    #pragma unroll
    for (int o = 16; o > 0; o >>= 1) {
        a += __shfl_down_sync(F, a, o);
        b += __shfl_down_sync(F, b, o);
        c += __shfl_down_sync(F, c, o);
    }
}

// DeepPoly relu diag from bounds
__device__ __forceinline__ void mk_diag(float l, float h, float& wlv, float& whv, float& brv) {
    bool cr = (l < 0.f) && (h > 0.f);
    float denom = cr ? (h - l) : 1.f;
    float ubs = cr ? h / denom : 0.f;
    float ubi = cr ? -(l * h) / denom : 0.f;
    float lam = (l * l > h * h) ? 0.f : 1.f;
    float keep = (h <= 0.f) ? 0.f : 1.f;
    whv = cr ? ubs : keep;
    wlv = cr ? lam : keep;
    brv = ubi;
}

// ---------------- small kernels ----------------
__global__ void normalize_k(const float* x, const float* lo, const float* hi,
                            float* x0, float* l0, float* h0, int n) {
    int i = blockIdx.x * blockDim.x + threadIdx.x;
    if (i < n) {
        x0[i] = (x[i] - MEANC) / STDC;
        l0[i] = (lo[i] - MEANC) / STDC;
        h0[i] = (hi[i] - MEANC) / STDC;
    }
}

// layer 0: warp-per-row fused matvec + box + diag0 + relu(x)
__global__ void box0_k(const float* __restrict__ W0, const float* __restrict__ x0,
                       const float* __restrict__ b0, const float* __restrict__ l0,
                       const float* __restrict__ h0, float* __restrict__ xa,
                       float* __restrict__ wl, float* __restrict__ wh,
                       float* __restrict__ bhr) {
    int w = threadIdx.x >> 5, lane = threadIdx.x & 31;
    int m = blockIdx.x * 8 + w;
    const float4* W4 = (const float4*)(W0 + (size_t)m * NIN);
    const float4* x4 = (const float4*)x0;
    const float4* l4 = (const float4*)l0;
    const float4* h4 = (const float4*)h0;
    float sx = 0.f, sh = 0.f, sl = 0.f;
    #pragma unroll
    for (int it = 0; it < 7; ++it) {
        int k4 = lane + it * 32;
        if (k4 < NIN / 4) {
            float4 wv = W4[k4], xv = x4[k4], lv = l4[k4], hv = h4[k4];
            #define P(c) { sx += wv.c * xv.c; \
                           sh += (wv.c >= 0.f) ? wv.c * hv.c : wv.c * lv.c; \
                           sl += (wv.c >= 0.f) ? wv.c * lv.c : wv.c * hv.c; }
            P(x) P(y) P(z) P(w)
            #undef P
        }
    }
    wred3(sx, sh, sl);
    if (lane == 0) {
        float bb = b0[m];
        float wlv, whv, brv;
        mk_diag(sl + bb, sh + bb, wlv, whv, brv);
        wl[m] = wlv; wh[m] = whv; bhr[m] = brv;
        xa[m] = fmaxf(sx + bb, 0.f);
    }
}

// chain start: warp-per-row fused matvec + relu-backsub transform, fp16 A emission.
__global__ void relu_bs_first_k(const float* __restrict__ W, const float* __restrict__ xin,
                                const float* __restrict__ bi,
                                const float* __restrict__ wld, const float* __restrict__ whd,
                                const float* __restrict__ bhrd, const float* __restrict__ bj,
                                __half* __restrict__ AH, __half* __restrict__ AL,
                                float* __restrict__ bh, float* __restrict__ bl,
                                float* __restrict__ xout,
                                float* __restrict__ lowv, float* __restrict__ highv,
                                int* __restrict__ cnt) {
    int w = threadIdx.x >> 5, lane = threadIdx.x & 31;
    int m = blockIdx.x * 8 + w;
    size_t base = (size_t)m * NH;
    const float4* W4 = (const float4*)(W + base);
    const float4* wl4 = (const float4*)wld;
    const float4* wh4 = (const float4*)whd;
    const float4* br4 = (const float4*)bhrd;
    const float4* bj4 = (const float4*)bj;
    const float4* x4 = (const float4*)xin;
    __half2* AH2 = (__half2*)(AH + base);
    __half2* AL2 = (__half2*)(AL + base);
    float sh = 0.f, sl = 0.f, sx = 0.f;
    #pragma unroll 4
    for (int it = 0; it < 16; ++it) {
        int k4 = lane + it * 32;
        float4 wv = W4[k4], whv = wh4[k4], wlv = wl4[k4], brv = br4[k4], bjv = bj4[k4], xv = x4[k4];
        float oh[4], ol[4];
        #define P(i, c) { float mask = (whv.c != 0.f) ? 1.f : 0.f; \
                          oh[i] = (wv.c > 0.f ? wv.c * whv.c : wv.c * wlv.c) * mask; \
                          ol[i] = (wv.c > 0.f ? wv.c * wlv.c : wv.c * whv.c) * mask; \
                          sh += fmaxf(wv.c, 0.f) * mask * brv.c + oh[i] * bjv.c; \
                          sl += fminf(wv.c, 0.f) * mask * brv.c + ol[i] * bjv.c; \
                          sx += wv.c * xv.c; }
        P(0, x) P(1, y) P(2, z) P(3, w)
        #undef P
        AH2[k4 * 2]     = __floats2half2_rn(oh[0], oh[1]);
        AH2[k4 * 2 + 1] = __floats2half2_rn(oh[2], oh[3]);
        AL2[k4 * 2]     = __floats2half2_rn(ol[0], ol[1]);
        AL2[k4 * 2 + 1] = __floats2half2_rn(ol[2], ol[3]);
    }
    wred3(sh, sl, sx);
    if (lane == 0) {
        float bb = bi[m];
        bh[m] = bb + sh;
        bl[m] = bb + sl;
        xout[m] = sx + bb;
    }
    if (threadIdx.x < 8) {
        int mm = blockIdx.x * 8 + threadIdx.x;
        lowv[mm] = 0.f;
        highv[mm] = 0.f;
    }
    if (blockIdx.x == 0 && threadIdx.x == 0) *cnt = 0;
}

// single-launch transpose of all 4 weights to fp16 (z = weight index)
__global__ void wsplit4_k(const float* __restrict__ W0, const float* __restrict__ W1,
                          const float* __restrict__ W2, const float* __restrict__ W3,
                          __half* __restrict__ WT) {
    int z = blockIdx.z;
    const float* W = (z == 0) ? W0 : (z == 1) ? W1 : (z == 2) ? W2 : W3;
    int fi = (z == 0) ? NIN : NH;
    __half* Th = WT + (size_t)z * NHNH;
    int nb = blockIdx.x * 32;
    if (z == 0 && nb >= 896) return;
    __shared__ float t[32][33];
    int tx = threadIdx.x, ty = threadIdx.y;
    int kb = blockIdx.y * 32;
    #pragma unroll
    for (int i = 0; i < 4; ++i) {
        int k = kb + ty + i * 8, n = nb + tx;
        t[ty + i * 8][tx] = (n < fi) ? W[(size_t)k * fi + n] : 0.f;
    }
    __syncthreads();
    #pragma unroll
    for (int i = 0; i < 4; ++i) {
        int n = nb + ty + i * 8, k = kb + tx;
        Th[(size_t)n * NH + k] = __float2half(t[tx][ty + i * 8]);
    }
}

// ---------------- layer-4 fused skinny chain ----------------
// One backsub step: reads prev NSEG-seg partials (or W4 direct), relu transform,
// bias atomics (+ layer-4 x-dot when Wfirst), GEMM vs W[j], writes new partials.
__global__ void __launch_bounds__(128) skfuse_k(
    const float* __restrict__ PinH, const float* __restrict__ PinL,
    const float* __restrict__ Wfirst, const float* __restrict__ xq,
    const float* __restrict__ wld, const float* __restrict__ whd,
    const float* __restrict__ bhrd, const float* __restrict__ bj,
    const float* __restrict__ Wj,
    float* __restrict__ PoutH, float* __restrict__ PoutL,
    float* __restrict__ bh, float* __restrict__ bl, float* __restrict__ x5, int Ng)
{
    __shared__ float sH[NOUT][128], sL[NOUT][128];
    const int t = threadIdx.x;
    const int seg = blockIdx.y;
    const int k0 = seg * 128;
    const bool dobias = (blockIdx.x == 0);
    float bHp[NOUT], bLp[NOUT], bXp[NOUT];
    #pragma unroll
    for (int m = 0; m < NOUT; ++m) { bHp[m] = 0.f; bLp[m] = 0.f; bXp[m] = 0.f; }

    {
        int k = k0 + t;
        float whk = whd[k], wlk = wld[k], brk = bhrd[k], bjk = bj[k];
        float mask = (whk != 0.f) ? 1.f : 0.f;
        float xqk = (Wfirst && dobias) ? xq[k] : 0.f;
        #pragma unroll
        for (int m = 0; m < NOUT; ++m) {
            float aH, aL;
            if (Wfirst) {
                aH = Wfirst[(size_t)m * NH + k];
                aL = aH;
            } else {
                aH = 0.f; aL = 0.f;
                #pragma unroll
                for (int s = 0; s < NSEG; ++s) {
                    aH += PinH[(size_t)(s * NOUT + m) * NH + k];
                    aL += PinL[(size_t)(s * NOUT + m) * NH + k];
                }
            }
            float oh = (aH > 0.f ? aH * whk : aH * wlk) * mask;
            float ol = (aL > 0.f ? aL * wlk : aL * whk) * mask;
            sH[m][t] = oh;
            sL[m][t] = ol;
            if (dobias) {
                bHp[m] += fmaxf(aH, 0.f) * mask * brk + oh * bjk;
                bLp[m] += fminf(aL, 0.f) * mask * brk + ol * bjk;
                if (Wfirst) bXp[m] += aH * xqk;
            }
        }
    }
    __syncthreads();

    if (dobias) {
        #pragma unroll
        for (int m = 0; m < NOUT; ++m) {
            float vH = bHp[m], vL = bLp[m], vX = bXp[m];
            wred3(vH, vL, vX);
            if ((t & 31) == 0) {
                atomicAdd(&bh[m], vH);
                atomicAdd(&bl[m], vL);
                if (Wfirst) atomicAdd(&x5[m], vX);
            }
        }
    }

    int n = blockIdx.x * 128 + t;
    if (n < Ng) {
        float aH[NOUT], aL[NOUT];
        #pragma unroll
        for (int m = 0; m < NOUT; ++m) { aH[m] = 0.f; aL[m] = 0.f; }
        for (int kk = 0; kk < 128; ++kk) {
            float w = Wj[(size_t)(k0 + kk) * Ng + n];
            #pragma unroll
            for (int m = 0; m < NOUT; ++m) { aH[m] += sH[m][kk] * w; aL[m] += sL[m][kk] * w; }
        }
        #pragma unroll
        for (int m = 0; m < NOUT; ++m) {
            PoutH[(size_t)(seg * NOUT + m) * NH + n] = aH[m];
            PoutL[(size_t)(seg * NOUT + m) * NH + n] = aL[m];
        }
    }
}

// final interval box over the NSEG partials; writes d_out directly
__global__ void boxp_k(const float* __restrict__ PH, const float* __restrict__ PL,
                       const float* __restrict__ bh, const float* __restrict__ bl,
                       const float* __restrict__ l0, const float* __restrict__ h0,
                       const float* __restrict__ x5, float* __restrict__ out) {
    int m = blockIdx.x;
    float sh = 0.f, sl = 0.f, d = 0.f;
    for (int n = threadIdx.x; n < NIN; n += blockDim.x) {
        float ah = 0.f, al = 0.f;
        #pragma unroll
        for (int s = 0; s < NSEG; ++s) {
            ah += PH[(size_t)(s * NOUT + m) * NH + n];
            al += PL[(size_t)(s * NOUT + m) * NH + n];
        }
        float l = l0[n], h = h0[n];
        sh += (ah >= 0.f) ? ah * h : ah * l;
        sl += (al >= 0.f) ? al * l : al * h;
    }
    // block reduce (2 values)
    const unsigned F = 0xffffffffu;
    #pragma unroll
    for (int o = 16; o > 0; o >>= 1) {
        sh += __shfl_down_sync(F, sh, o);
        sl += __shfl_down_sync(F, sl, o);
    }
    __shared__ float rh[8], rl[8];
    int w = threadIdx.x >> 5, lane = threadIdx.x & 31;
    if (lane == 0) { rh[w] = sh; rl[w] = sl; }
    __syncthreads();
    if (threadIdx.x == 0) {
        sh = 0.f; sl = 0.f;
        for (int i = 0; i < (int)(blockDim.x >> 5); ++i) { sh += rh[i]; sl += rl[i]; }
        out[m] = x5[m];
        out[NOUT + m] = bl[m] + sl;
        out[2 * NOUT + m] = bh[m] + sh;
    }
    (void)d;
}

// ---------------- fused H/L fp16 GEMM with transform/box epilogue ----------------
#define ROWB  272
#define MATB  (128 * ROWB)
#define STAGE (3 * MATB)
#define GSMEM (2 * STAGE)

__device__ __forceinline__ void ldsm4(uint32_t* r, uint32_t addr) {
    asm volatile("ldmatrix.sync.aligned.m8n8.x4.shared.b16 {%0,%1,%2,%3}, [%4];"
                 : "=r"(r[0]), "=r"(r[1]), "=r"(r[2]), "=r"(r[3]) : "r"(addr));
}
__device__ __forceinline__ void mma16816(float* c, const uint32_t* a, const uint32_t* b) {
    asm volatile(
        "mma.sync.aligned.m16n8k16.row.col.f32.f16.f16.f32 "
        "{%0,%1,%2,%3}, {%4,%5,%6,%7}, {%8,%9}, {%0,%1,%2,%3};"
        : "+f"(c[0]), "+f"(c[1]), "+f"(c[2]), "+f"(c[3])
        : "r"(a[0]), "r"(a[1]), "r"(a[2]), "r"(a[3]), "r"(b[0]), "r"(b[1]));
}

__device__ __forceinline__ void issue_chunk(uint32_t sb, int slot,
                                            const __half* Af, const __half* B,
                                            int row0, int col0, int k0, int tid) {
    uint32_t sbase = sb + slot * STAGE;
    #pragma unroll
    for (int i = 0; i < 24; ++i) {
        int q = tid + (i << 8);
        int mat = q >> 11;
        int r = (q >> 4) & 127;
        int g = q & 15;
        const __half* src;
        int grow;
        if (mat < 2) { src = Af + ((size_t)mat << 22); grow = row0 + r; }
        else         { src = B;                        grow = col0 + r; }
        const void* gp = src + (size_t)grow * NH + k0 + (g << 3);
        uint32_t sp = sbase + mat * MATB + r * ROWB + (g << 4);
        asm volatile("cp.async.cg.shared.global [%0], [%1], 16;" :: "r"(sp), "l"(gp));
    }
    asm volatile("cp.async.commit_group;" ::: "memory");
}

__global__ void __launch_bounds__(256, 1) hgemm_k(const __half* __restrict__ Af,
                                               const __half* __restrict__ B,
                                               __half* __restrict__ AoutH, __half* __restrict__ AoutL,
                                               const float* __restrict__ wld, const float* __restrict__ whd,
                                               const float* __restrict__ bhrd, const float* __restrict__ bjv,
                                               float* __restrict__ bh, float* __restrict__ bl,
                                               const float* __restrict__ l0, const float* __restrict__ h0,
                                               float* __restrict__ lowv, float* __restrict__ highv,
                                               int Ng, int mode,
                                               float* __restrict__ dwl, float* __restrict__ dwh,
                                               float* __restrict__ dbhr, float* __restrict__ xvec,
                                               const float* __restrict__ b4v, float* __restrict__ x5v,
                                               int* __restrict__ cnt) {
    extern __shared__ char smem[];
    const uint32_t sb = smem_u32(smem);
    const int tid = threadIdx.x, lane = tid & 31, wid = tid >> 5;
    const int row0 = blockIdx.y * 128, col0 = blockIdx.x * 128;
    const int half = wid >> 2, wq = wid & 3;
    const int warpM = (wq & 1) << 6, warpN = (wq >> 1) << 6;

    float acc[4][8][4];
    #pragma unroll
    for (int mi = 0; mi < 4; ++mi)
        #pragma unroll
        for (int ni = 0; ni < 8; ++ni)
            #pragma unroll
            for (int e = 0; e < 4; ++e) acc[mi][ni][e] = 0.f;

    issue_chunk(sb, 0, Af, B, row0, col0, 0, tid);

    const uint32_t aoff = (uint32_t)((lane & 15) * ROWB + ((lane >> 4) << 4));
    const uint32_t boff = (uint32_t)(((((lane >> 4) & 1) << 3) + (lane & 7)) * ROWB + (((lane >> 3) & 1) << 4));

    uint32_t A0[4][4], B0[4][4], A1[4][4], B1[4][4];

    const int CHUNKS = 16;
    for (int c = 0; c < CHUNKS; ++c) {
        asm volatile("cp.async.wait_group 0;" ::: "memory");
        __syncthreads();
        if (c + 1 < CHUNKS)
            issue_chunk(sb, (c + 1) & 1, Af, B, row0, col0, (c + 1) * 128, tid);

        uint32_t st = sb + (c & 1) * STAGE;
        uint32_t sA = st + half * MATB + warpM * ROWB + aoff;
        uint32_t sB = st + 2 * MATB + warpN * ROWB + boff;

        #define LDF(Ab, Bb, ko) do { \
            _Pragma("unroll") \
            for (int mi = 0; mi < 4; ++mi) ldsm4(Ab[mi], sA + mi * (16 * ROWB) + (ko)); \
            _Pragma("unroll") \
            for (int pi = 0; pi < 4; ++pi) ldsm4(Bb[pi], sB + pi * (16 * ROWB) + (ko)); \
        } while (0)
        #define MMAF(Ab, Bb) do { \
            _Pragma("unroll") \
            for (int mi = 0; mi < 4; ++mi) \
                _Pragma("unroll") \
                for (int ni = 0; ni < 8; ++ni) \
                    mma16816(acc[mi][ni], Ab[mi], &Bb[ni >> 1][(ni & 1) << 1]); \
        } while (0)

        LDF(A0, B0, 0);
        LDF(A1, B1, 32);
        MMAF(A0, B0);
        LDF(A0, B0, 64);
        MMAF(A1, B1);
        LDF(A1, B1, 96);
        MMAF(A0, B0);
        LDF(A0, B0, 128);
        MMAF(A1, B1);
        LDF(A1, B1, 160);
        MMAF(A0, B0);
        LDF(A0, B0, 192);
        MMAF(A1, B1);
        LDF(A1, B1, 224);
        MMAF(A0, B0);
        MMAF(A1, B1);
        #undef LDF
        #undef MMAF
    }

    float rowsum[4][2];
    #pragma unroll
    for (int mi = 0; mi < 4; ++mi) { rowsum[mi][0] = 0.f; rowsum[mi][1] = 0.f; }

    if (mode == 1) {
        __half* Aout = half ? AoutL : AoutH;
        #pragma unroll
        for (int ni = 0; ni < 8; ++ni) {
            int gc = col0 + warpN + ni * 8 + ((lane & 3) << 1);
            float wh0 = whd[gc], wh1 = whd[gc + 1];
            float wl0 = wld[gc], wl1 = wld[gc + 1];
            float br0 = bhrd[gc], br1 = bhrd[gc + 1];
            float bj0 = bjv[gc], bj1 = bjv[gc + 1];
            float m0 = (wh0 != 0.f) ? 1.f : 0.f, m1 = (wh1 != 0.f) ? 1.f : 0.f;
            #pragma unroll
            for (int mi = 0; mi < 4; ++mi)
                #pragma unroll
                for (int e = 0; e < 2; ++e) {
                    float v0 = acc[mi][ni][2 * e], v1 = acc[mi][ni][2 * e + 1];
                    float t0, t1, s;
                    if (half == 0) {
                        t0 = (v0 > 0.f ? v0 * wh0 : v0 * wl0) * m0;
                        t1 = (v1 > 0.f ? v1 * wh1 : v1 * wl1) * m1;
                        s = fmaxf(v0, 0.f) * m0 * br0 + t0 * bj0 + fmaxf(v1, 0.f) * m1 * br1 + t1 * bj1;
                    } else {
                        t0 = (v0 > 0.f ? v0 * wl0 : v0 * wh0) * m0;
                        t1 = (v1 > 0.f ? v1 * wl1 : v1 * wh1) * m1;
                        s = fminf(v0, 0.f) * m0 * br0 + t0 * bj0 + fminf(v1, 0.f) * m1 * br1 + t1 * bj1;
                    }
                    rowsum[mi][e] += s;
                    int gr = row0 + warpM + mi * 16 + (lane >> 2) + e * 8;
                    *reinterpret_cast<__half2*>(Aout + (size_t)gr * NH + gc) = __floats2half2_rn(t0, t1);
                }
        }
        float* bacc = half ? bl : bh;
        #pragma unroll
        for (int mi = 0; mi < 4; ++mi)
            #pragma unroll
            for (int e = 0; e < 2; ++e) {
                float s = rowsum[mi][e];
                s += __shfl_xor_sync(0xffffffffu, s, 1);
                s += __shfl_xor_sync(0xffffffffu, s, 2);
                if ((lane & 3) == 0) {
                    int gr = row0 + warpM + mi * 16 + (lane >> 2) + e * 8;
                    atomicAdd(&bacc[gr], s);
                }
            }
    } else {
        #pragma unroll
        for (int ni = 0; ni < 8; ++ni) {
            int gc = col0 + warpN + ni * 8 + ((lane & 3) << 1);
            float L0 = (gc < Ng) ? l0[gc] : 0.f;
            float H0 = (gc < Ng) ? h0[gc] : 0.f;
            float L1 = (gc + 1 < Ng) ? l0[gc + 1] : 0.f;
            float H1 = (gc + 1 < Ng) ? h0[gc + 1] : 0.f;
            #pragma unroll
            for (int mi = 0; mi < 4; ++mi)
                #pragma unroll
                for (int e = 0; e < 2; ++e) {
                    float v0 = acc[mi][ni][2 * e], v1 = acc[mi][ni][2 * e + 1];
                    float s;
                    if (half == 0)
                        s = (v0 >= 0.f ? v0 * H0 : v0 * L0) + (v1 >= 0.f ? v1 * H1 : v1 * L1);
                    else
                        s = (v0 >= 0.f ? v0 * L0 : v0 * H0) + (v1 >= 0.f ? v1 * L1 : v1 * H1);
                    rowsum[mi][e] += s;
                }
        }
        float* outv = half ? lowv : highv;
        #pragma unroll
        for (int mi = 0; mi < 4; ++mi)
            #pragma unroll
            for (int e = 0; e < 2; ++e) {
                float s = rowsum[mi][e];
                s += __shfl_xor_sync(0xffffffffu, s, 1);
                s += __shfl_xor_sync(0xffffffffu, s, 2);
                if ((lane & 3) == 0) {
                    int gr = row0 + warpM + mi * 16 + (lane >> 2) + e * 8;
                    atomicAdd(&outv[gr], s);
                }
            }

        // ---- last-CTA tail: relu diag for this layer, relu x, seed layer-4 state ----
        __threadfence();
        __shared__ int lastf;
        if (tid == 0)
            lastf = (atomicAdd(cnt, 1) == (int)(gridDim.x * gridDim.y - 1)) ? 1 : 0;
        __syncthreads();
        if (lastf) {
            __threadfence();
            for (int k = tid; k < NH; k += 256) {
                float l = lowv[k] + bl[k];
                float h = highv[k] + bh[k];
                float wlv, whv, brv;
                mk_diag(l, h, wlv, whv, brv);
                dwl[k] = wlv; dwh[k] = whv; dbhr[k] = brv;
                xvec[k] = fmaxf(xvec[k], 0.f);
            }
            if (b4v) {
                __syncthreads();
                if (tid < NOUT) {
                    bh[tid] = b4v[tid];
                    bl[tid] = b4v[tid];
                    x5v[tid] = b4v[tid];
                }
            }
        }
    }
}

// ---------------- driver ----------------
extern "C" void kernel_launch(void* const* d_in, const int* in_sizes, int n_in,
                              void* d_out, int out_size) {
    const float* x  = (const float*)d_in[0];
    const float* lo = (const float*)d_in[1];
    const float* hi = (const float*)d_in[2];
    const float* W[5];
    const float* b[5];
    for (int i = 0; i < 5; ++i) { W[i] = (const float*)d_in[3 + 2 * i]; b[i] = (const float*)d_in[4 + 2 * i]; }
    float* out = (float*)d_out;

    cudaFuncSetAttribute(hgemm_k, cudaFuncAttributeMaxDynamicSharedMemorySize, GSMEM);

    void* p;
    __half *Af, *WT;
    cudaGetSymbolAddress(&p, g_Af); Af = (__half*)p;
    cudaGetSymbolAddress(&p, g_WT); WT = (__half*)p;
    float* P0;
    cudaGetSymbolAddress(&p, g_part); P0 = (float*)p;
    size_t q = (size_t)NSEG * NOUT * NH;
    float* P0H = P0;
    float* P0L = P0 + q;
    float* P1H = (float*)Af;            // g_Af free during layer-4 chain
    float* P1L = (float*)Af + q;
    float *xa, *xb, *lowv, *highv, *wl, *wh, *bhr, *bh, *bl, *x0, *l0, *h0, *x5;
    int* cnt;
    cudaGetSymbolAddress(&p, g_xa);   xa = (float*)p;
    cudaGetSymbolAddress(&p, g_xb);   xb = (float*)p;
    cudaGetSymbolAddress(&p, g_low);  lowv = (float*)p;
    cudaGetSymbolAddress(&p, g_high); highv = (float*)p;
    cudaGetSymbolAddress(&p, g_wl);   wl = (float*)p;
    cudaGetSymbolAddress(&p, g_wh);   wh = (float*)p;
    cudaGetSymbolAddress(&p, g_bhr);  bhr = (float*)p;
    cudaGetSymbolAddress(&p, g_bh);   bh = (float*)p;
    cudaGetSymbolAddress(&p, g_bl);   bl = (float*)p;
    cudaGetSymbolAddress(&p, g_x0);   x0 = (float*)p;
    cudaGetSymbolAddress(&p, g_l0);   l0 = (float*)p;
    cudaGetSymbolAddress(&p, g_h0);   h0 = (float*)p;
    cudaGetSymbolAddress(&p, g_x5);   x5 = (float*)p;
    cudaGetSymbolAddress(&p, g_cnt);  cnt = (int*)p;

    normalize_k<<<(NIN + 255) / 256, 256>>>(x, lo, hi, x0, l0, h0, NIN);
    wsplit4_k<<<dim3(64, 64, 4), dim3(32, 8)>>>(W[0], W[1], W[2], W[3], WT);

    // layer 0
    box0_k<<<NH / 8, 256>>>(W[0], x0, b[0], l0, h0, xa, wl, wh, bhr);

    float* xin = xa;
    float* xout = xb;
    for (int i = 1; i < 4; ++i) {
        int cur = 0;
        relu_bs_first_k<<<NH / 8, 256>>>(W[i], xin, b[i],
                                         wl + (i - 1) * NH, wh + (i - 1) * NH, bhr + (i - 1) * NH, b[i - 1],
                                         Af, Af + (size_t)NHNH, bh, bl, xout, lowv, highv, cnt);
        for (int j = i - 1; j >= 1; --j) {
            __half* Ain = Af + (size_t)cur * 2 * NHNH;
            __half* AoH = Af + (size_t)(cur ^ 1) * 2 * NHNH;
            hgemm_k<<<dim3(16, 16), 256, GSMEM>>>(Ain, WT + (size_t)j * NHNH,
                                                  AoH, AoH + (size_t)NHNH,
                                                  wl + (j - 1) * NH, wh + (j - 1) * NH,
                                                  bhr + (j - 1) * NH, b[j - 1],
                                                  bh, bl, nullptr, nullptr, nullptr, nullptr,
                                                  NH, 1,
                                                  nullptr, nullptr, nullptr, nullptr,
                                                  nullptr, nullptr, nullptr);
            cur ^= 1;
        }
        {
            __half* Ain = Af + (size_t)cur * 2 * NHNH;
            hgemm_k<<<dim3(7, 16), 256, GSMEM>>>(Ain, WT,
                                                 nullptr, nullptr,
                                                 nullptr, nullptr, nullptr, nullptr,
                                                 bh, bl, l0, h0, lowv, highv,
                                                 NIN, 2,
                                                 wl + i * NH, wh + i * NH, bhr + i * NH, xout,
                                                 (i == 3) ? b[4] : nullptr, x5, cnt);
        }
        float* t = xin; xin = xout; xout = t;
    }

    // layer 4 (M=10): fused fp32 skinny chain (bh/bl/x5 seeded by chain-3 box tail)
    {
        int cur = 0;
        float* PHs[2] = { P0H, P1H };
        float* PLs[2] = { P0L, P1L };
        skfuse_k<<<dim3(16, NSEG), 128>>>(nullptr, nullptr, W[4], xin,
                                          wl + 3 * NH, wh + 3 * NH, bhr + 3 * NH, b[3],
                                          W[3], PHs[cur], PLs[cur], bh, bl, x5, NH);
        for (int j = 2; j >= 1; --j) {
            skfuse_k<<<dim3(16, NSEG), 128>>>(PHs[cur], PLs[cur], nullptr, nullptr,
                                              wl + j * NH, wh + j * NH, bhr + j * NH, b[j],
                                              W[j], PHs[cur ^ 1], PLs[cur ^ 1], bh, bl, x5, NH);
            cur ^= 1;
        }
        skfuse_k<<<dim3(7, NSEG), 128>>>(PHs[cur], PLs[cur], nullptr, nullptr,
                                         wl, wh, bhr, b[0],
                                         W[0], PHs[cur ^ 1], PLs[cur ^ 1], bh, bl, x5, NIN);
        cur ^= 1;
        boxp_k<<<NOUT, 256>>>(PHs[cur], PLs[cur], bh, bl, l0, h0, x5, out);
    }
    (void)in_sizes; (void)n_in; (void)out_size;
}